// round 1
// baseline (speedup 1.0000x reference)
#include <cuda_runtime.h>

#define NMAX 100000
#define EMAX 1600000
#define FIN  11
#define HDIM 128
#define DOUT 64
#define LNEPS 1e-5f

// ---------------- scratch (static device globals; no runtime allocation) ----------------
__device__ float g_deg [NMAX];
__device__ float g_aggF[NMAX * FIN];
__device__ float g_h0  [NMAX * HDIM];
__device__ float g_agg1[NMAX * HDIM];
__device__ float g_h1  [NMAX * HDIM];
__device__ float g_xt2 [NMAX * DOUT];
__device__ float g_agg2[NMAX * DOUT];

// ---------------- zero accumulators ----------------
__global__ void zero_kernel(int N) {
    long long i      = (long long)blockIdx.x * blockDim.x + threadIdx.x;
    long long stride = (long long)gridDim.x * blockDim.x;
    for (long long k = i; k < N; k += stride) g_deg[k] = 0.f;
    for (long long k = i; k < (long long)N * FIN; k += stride) g_aggF[k] = 0.f;
    float4 z = make_float4(0.f, 0.f, 0.f, 0.f);
    float4* a1 = (float4*)g_agg1;
    long long n1 = (long long)N * HDIM / 4;
    for (long long k = i; k < n1; k += stride) a1[k] = z;
    float4* a2 = (float4*)g_agg2;
    long long n2 = (long long)N * DOUT / 4;
    for (long long k = i; k < n2; k += stride) a2[k] = z;
}

// ---------------- degree + layer-0 aggregation (11-dim input space) ----------------
__global__ void edge_deg_agg0(const float* __restrict__ nf, const int* __restrict__ ei, int E) {
    int e = blockIdx.x * blockDim.x + threadIdx.x;
    if (e >= E) return;
    int s = ei[e], t = ei[E + e];
    atomicAdd(&g_deg[t], 1.0f);
    const float* x = nf + (long long)s * FIN;
    float* a = g_aggF + (long long)t * FIN;
#pragma unroll
    for (int i = 0; i < FIN; i++) atomicAdd(a + i, x[i]);
}

// ---------------- conv0: (aggF/deg) @ W0^T + b0 -> LN -> ReLU -> h0  (warp per node) ----------------
__global__ void conv0_kernel(const float* __restrict__ W0, const float* __restrict__ b0,
                             const float* __restrict__ g0, const float* __restrict__ be0, int N) {
    __shared__ float sW[HDIM * FIN];
    __shared__ float sb[HDIM], sg[HDIM], sbe[HDIM];
    for (int i = threadIdx.x; i < HDIM * FIN; i += blockDim.x) sW[i] = W0[i];
    for (int i = threadIdx.x; i < HDIM; i += blockDim.x) { sb[i] = b0[i]; sg[i] = g0[i]; sbe[i] = be0[i]; }
    __syncthreads();
    int lane   = threadIdx.x & 31;
    int gwarp  = (blockIdx.x * blockDim.x + threadIdx.x) >> 5;
    int nwarps = (gridDim.x * blockDim.x) >> 5;
    for (int node = gwarp; node < N; node += nwarps) {
        float dg  = g_deg[node];
        float inv = dg > 0.f ? 1.f / dg : 0.f;
        float m[FIN];
#pragma unroll
        for (int i = 0; i < FIN; i++) m[i] = g_aggF[(long long)node * FIN + i] * inv;
        float v[4];
#pragma unroll
        for (int r = 0; r < 4; r++) {
            int j = lane + 32 * r;
            float acc = sb[j];
#pragma unroll
            for (int i = 0; i < FIN; i++) acc = fmaf(m[i], sW[j * FIN + i], acc);
            v[r] = (dg > 0.f) ? acc : 0.f;  // deg==0: reference conv output is exactly 0
        }
        float s  = v[0] + v[1] + v[2] + v[3];
        float s2 = v[0] * v[0] + v[1] * v[1] + v[2] * v[2] + v[3] * v[3];
#pragma unroll
        for (int o = 16; o; o >>= 1) {
            s  += __shfl_xor_sync(0xffffffffu, s,  o);
            s2 += __shfl_xor_sync(0xffffffffu, s2, o);
        }
        float mu  = s * (1.f / HDIM);
        float var = s2 * (1.f / HDIM) - mu * mu;
        float rs  = rsqrtf(var + LNEPS);
#pragma unroll
        for (int r = 0; r < 4; r++) {
            int j = lane + 32 * r;
            float y = (v[r] - mu) * rs * sg[j] + sbe[j];
            g_h0[(long long)node * HDIM + j] = fmaxf(y, 0.f);
        }
    }
}

// ---------------- edge aggregation, 128-wide: warp per edge, float4 per lane ----------------
__global__ void edge_agg1(const int* __restrict__ ei, int E) {
    long long idx = (long long)blockIdx.x * blockDim.x + threadIdx.x;
    int e = (int)(idx >> 5);
    if (e >= E) return;
    int lane = (int)(idx & 31);
    int s = ei[e], t = ei[E + e];
    float4 v = *(const float4*)(g_h0 + (long long)s * HDIM + lane * 4);
    float* d = g_agg1 + (long long)t * HDIM + lane * 4;
    atomicAdd(d + 0, v.x); atomicAdd(d + 1, v.y);
    atomicAdd(d + 2, v.z); atomicAdd(d + 3, v.w);
}

// ---------------- conv1: (agg1/deg) @ W1^T + b1 -> LN -> ReLU -> h1 ----------------
// W1 transposed into smem (pitch 132 to keep float4 reads conflict-free); 4 nodes per warp
// per iteration so W reads amortize and the loop is FFMA-bound.
#define W1PITCH 132
#define CONV1_SMEM ((HDIM * W1PITCH + 8 * 4 * HDIM + 3 * HDIM) * 4)
__global__ void conv1_kernel(const float* __restrict__ W, const float* __restrict__ b,
                             const float* __restrict__ gg, const float* __restrict__ be, int N) {
    extern __shared__ float smem[];
    float* Wt  = smem;                    // [128][132]
    float* sM  = Wt + HDIM * W1PITCH;     // [8 warps][4 nodes * 128]
    float* sb  = sM + 8 * 4 * HDIM;
    float* sg  = sb + HDIM;
    float* sbe = sg + HDIM;
    int tid = threadIdx.x;
    for (int i = tid; i < HDIM * HDIM; i += blockDim.x) {
        int j = i >> 7, k = i & 127;      // W[j][k]
        Wt[k * W1PITCH + j] = W[i];
    }
    for (int i = tid; i < HDIM; i += blockDim.x) { sb[i] = b[i]; sg[i] = gg[i]; sbe[i] = be[i]; }
    __syncthreads();
    int warp = tid >> 5, lane = tid & 31;
    float* mw = sM + warp * 4 * HDIM;
    long long gwarp = blockIdx.x * 8 + warp;
    long long nw    = (long long)gridDim.x * 8;
    for (long long base = gwarp * 4; base < N; base += nw * 4) {
        __syncwarp();
        float msk[4];
#pragma unroll
        for (int q = 0; q < 4; q++) {
            long long node = base + q;
            float4 v = make_float4(0.f, 0.f, 0.f, 0.f);
            float mk = 0.f;
            if (node < N) {
                float dg  = g_deg[node];
                float inv = dg > 0.f ? 1.f / dg : 0.f;
                mk = dg > 0.f ? 1.f : 0.f;
                v = *(const float4*)(g_agg1 + node * HDIM + lane * 4);
                v.x *= inv; v.y *= inv; v.z *= inv; v.w *= inv;
            }
            msk[q] = mk;
            *(float4*)(mw + q * HDIM + lane * 4) = v;
        }
        __syncwarp();
        float4 b4 = *(const float4*)&sb[lane * 4];
        float acc[4][4];
#pragma unroll
        for (int q = 0; q < 4; q++) { acc[q][0] = b4.x; acc[q][1] = b4.y; acc[q][2] = b4.z; acc[q][3] = b4.w; }
        for (int k = 0; k < HDIM; k += 4) {
            float4 w0 = *(const float4*)&Wt[(k + 0) * W1PITCH + lane * 4];
            float4 w1 = *(const float4*)&Wt[(k + 1) * W1PITCH + lane * 4];
            float4 w2 = *(const float4*)&Wt[(k + 2) * W1PITCH + lane * 4];
            float4 w3 = *(const float4*)&Wt[(k + 3) * W1PITCH + lane * 4];
#pragma unroll
            for (int q = 0; q < 4; q++) {
                float4 mq = *(const float4*)(mw + q * HDIM + k);   // warp-broadcast LDS.128
                acc[q][0] = fmaf(mq.x, w0.x, acc[q][0]); acc[q][1] = fmaf(mq.x, w0.y, acc[q][1]);
                acc[q][2] = fmaf(mq.x, w0.z, acc[q][2]); acc[q][3] = fmaf(mq.x, w0.w, acc[q][3]);
                acc[q][0] = fmaf(mq.y, w1.x, acc[q][0]); acc[q][1] = fmaf(mq.y, w1.y, acc[q][1]);
                acc[q][2] = fmaf(mq.y, w1.z, acc[q][2]); acc[q][3] = fmaf(mq.y, w1.w, acc[q][3]);
                acc[q][0] = fmaf(mq.z, w2.x, acc[q][0]); acc[q][1] = fmaf(mq.z, w2.y, acc[q][1]);
                acc[q][2] = fmaf(mq.z, w2.z, acc[q][2]); acc[q][3] = fmaf(mq.z, w2.w, acc[q][3]);
                acc[q][0] = fmaf(mq.w, w3.x, acc[q][0]); acc[q][1] = fmaf(mq.w, w3.y, acc[q][1]);
                acc[q][2] = fmaf(mq.w, w3.z, acc[q][2]); acc[q][3] = fmaf(mq.w, w3.w, acc[q][3]);
            }
        }
        float4 g4  = *(const float4*)&sg[lane * 4];
        float4 be4 = *(const float4*)&sbe[lane * 4];
#pragma unroll
        for (int q = 0; q < 4; q++) {
            if (base + q >= N) break;
            float v0 = acc[q][0] * msk[q], v1 = acc[q][1] * msk[q];
            float v2 = acc[q][2] * msk[q], v3 = acc[q][3] * msk[q];
            float s  = v0 + v1 + v2 + v3;
            float s2 = v0 * v0 + v1 * v1 + v2 * v2 + v3 * v3;
#pragma unroll
            for (int o = 16; o; o >>= 1) {
                s  += __shfl_xor_sync(0xffffffffu, s,  o);
                s2 += __shfl_xor_sync(0xffffffffu, s2, o);
            }
            float mu  = s * (1.f / HDIM);
            float var = s2 * (1.f / HDIM) - mu * mu;
            float rs  = rsqrtf(var + LNEPS);
            float4 o4;
            o4.x = fmaxf((v0 - mu) * rs * g4.x + be4.x, 0.f);
            o4.y = fmaxf((v1 - mu) * rs * g4.y + be4.y, 0.f);
            o4.z = fmaxf((v2 - mu) * rs * g4.z + be4.z, 0.f);
            o4.w = fmaxf((v3 - mu) * rs * g4.w + be4.w, 0.f);
            *(float4*)(g_h1 + (base + q) * HDIM + lane * 4) = o4;
        }
    }
}

// ---------------- gemm2: xt2 = h1 @ W2^T + b2  (128 -> 64, no LN; aggregation follows) ----------------
#define W2PITCH 66
#define GEMM2_SMEM ((HDIM * W2PITCH + 8 * 4 * HDIM + DOUT) * 4)
__global__ void gemm2_kernel(const float* __restrict__ W, const float* __restrict__ b, int N) {
    extern __shared__ float smem[];
    float* Wt = smem;                   // [128][66], 64 outputs
    float* sM = Wt + HDIM * W2PITCH;
    float* sb = sM + 8 * 4 * HDIM;
    int tid = threadIdx.x;
    for (int i = tid; i < DOUT * HDIM; i += blockDim.x) {
        int j = i >> 7, k = i & 127;    // W2[j][k], j < 64
        Wt[k * W2PITCH + j] = W[i];
    }
    for (int i = tid; i < DOUT; i += blockDim.x) sb[i] = b[i];
    __syncthreads();
    int warp = tid >> 5, lane = tid & 31;
    float* mw = sM + warp * 4 * HDIM;
    long long gwarp = blockIdx.x * 8 + warp;
    long long nw    = (long long)gridDim.x * 8;
    for (long long base = gwarp * 4; base < N; base += nw * 4) {
        __syncwarp();
#pragma unroll
        for (int q = 0; q < 4; q++) {
            long long node = base + q;
            float4 v = make_float4(0.f, 0.f, 0.f, 0.f);
            if (node < N) v = *(const float4*)(g_h1 + node * HDIM + lane * 4);
            *(float4*)(mw + q * HDIM + lane * 4) = v;
        }
        __syncwarp();
        float2 b2v = *(const float2*)&sb[lane * 2];
        float acc[4][2];
#pragma unroll
        for (int q = 0; q < 4; q++) { acc[q][0] = b2v.x; acc[q][1] = b2v.y; }
        for (int k = 0; k < HDIM; k += 4) {
            float2 w0 = *(const float2*)&Wt[(k + 0) * W2PITCH + lane * 2];
            float2 w1 = *(const float2*)&Wt[(k + 1) * W2PITCH + lane * 2];
            float2 w2 = *(const float2*)&Wt[(k + 2) * W2PITCH + lane * 2];
            float2 w3 = *(const float2*)&Wt[(k + 3) * W2PITCH + lane * 2];
#pragma unroll
            for (int q = 0; q < 4; q++) {
                float4 mq = *(const float4*)(mw + q * HDIM + k);
                acc[q][0] = fmaf(mq.x, w0.x, acc[q][0]); acc[q][1] = fmaf(mq.x, w0.y, acc[q][1]);
                acc[q][0] = fmaf(mq.y, w1.x, acc[q][0]); acc[q][1] = fmaf(mq.y, w1.y, acc[q][1]);
                acc[q][0] = fmaf(mq.z, w2.x, acc[q][0]); acc[q][1] = fmaf(mq.z, w2.y, acc[q][1]);
                acc[q][0] = fmaf(mq.w, w3.x, acc[q][0]); acc[q][1] = fmaf(mq.w, w3.y, acc[q][1]);
            }
        }
#pragma unroll
        for (int q = 0; q < 4; q++) {
            if (base + q >= N) break;
            float2 o; o.x = acc[q][0]; o.y = acc[q][1];
            *(float2*)(g_xt2 + (base + q) * DOUT + lane * 2) = o;
        }
    }
}

// ---------------- edge aggregation, 64-wide: 16 threads per edge ----------------
__global__ void edge_agg2(const int* __restrict__ ei, int E) {
    long long idx = (long long)blockIdx.x * blockDim.x + threadIdx.x;
    int e = (int)(idx >> 4);
    if (e >= E) return;
    int su = (int)(idx & 15);
    int s = ei[e], t = ei[E + e];
    float4 v = *(const float4*)(g_xt2 + (long long)s * DOUT + su * 4);
    float* d = g_agg2 + (long long)t * DOUT + su * 4;
    atomicAdd(d + 0, v.x); atomicAdd(d + 1, v.y);
    atomicAdd(d + 2, v.z); atomicAdd(d + 3, v.w);
}

// ---------------- final: agg2/max(deg,1) -> LN -> out ----------------
__global__ void final_kernel(const float* __restrict__ g2, const float* __restrict__ be2,
                             float* __restrict__ out, int N) {
    int lane   = threadIdx.x & 31;
    int gwarp  = (blockIdx.x * blockDim.x + threadIdx.x) >> 5;
    int nwarps = (gridDim.x * blockDim.x) >> 5;
    float gA = g2[lane * 2], gB = g2[lane * 2 + 1];
    float bA = be2[lane * 2], bB = be2[lane * 2 + 1];
    for (int node = gwarp; node < N; node += nwarps) {
        float dg  = g_deg[node];
        float inv = dg > 0.f ? 1.f / dg : 1.f;     // reference: deg==0 -> divide by 1 (agg is 0)
        float2 v = *(const float2*)(g_agg2 + (long long)node * DOUT + lane * 2);
        v.x *= inv; v.y *= inv;
        float s = v.x + v.y, s2 = v.x * v.x + v.y * v.y;
#pragma unroll
        for (int o = 16; o; o >>= 1) {
            s  += __shfl_xor_sync(0xffffffffu, s,  o);
            s2 += __shfl_xor_sync(0xffffffffu, s2, o);
        }
        float mu  = s * (1.f / DOUT);
        float var = s2 * (1.f / DOUT) - mu * mu;
        float rs  = rsqrtf(var + LNEPS);
        float2 o2;
        o2.x = (v.x - mu) * rs * gA + bA;
        o2.y = (v.y - mu) * rs * gB + bB;
        *(float2*)(out + (long long)node * DOUT + lane * 2) = o2;
    }
}

// ---------------- launch ----------------
extern "C" void kernel_launch(void* const* d_in, const int* in_sizes, int n_in,
                              void* d_out, int out_size) {
    const float* nf  = (const float*)d_in[0];
    const int*   ei  = (const int*)d_in[1];
    const float* W0  = (const float*)d_in[2];
    const float* b0  = (const float*)d_in[3];
    const float* W1  = (const float*)d_in[4];
    const float* b1  = (const float*)d_in[5];
    const float* W2  = (const float*)d_in[6];
    const float* b2  = (const float*)d_in[7];
    const float* g0  = (const float*)d_in[8];
    const float* be0 = (const float*)d_in[9];
    const float* g1  = (const float*)d_in[10];
    const float* be1 = (const float*)d_in[11];
    const float* g2  = (const float*)d_in[12];
    const float* be2 = (const float*)d_in[13];
    int N = in_sizes[0] / FIN;
    int E = in_sizes[1] / 2;

    cudaFuncSetAttribute(conv1_kernel, cudaFuncAttributeMaxDynamicSharedMemorySize, CONV1_SMEM);
    cudaFuncSetAttribute(gemm2_kernel, cudaFuncAttributeMaxDynamicSharedMemorySize, GEMM2_SMEM);

    zero_kernel<<<2048, 256>>>(N);
    edge_deg_agg0<<<(E + 255) / 256, 256>>>(nf, ei, E);
    conv0_kernel<<<1480, 256>>>(W0, b0, g0, be0, N);
    edge_agg1<<<(E * 32 + 255) / 256, 256>>>(ei, E);
    conv1_kernel<<<1480, 256, CONV1_SMEM>>>(W1, b1, g1, be1, N);
    gemm2_kernel<<<1480, 256, GEMM2_SMEM>>>(W2, b2, N);
    edge_agg2<<<(E * 16 + 255) / 256, 256>>>(ei, E);
    final_kernel<<<1480, 256>>>(g2, be2, (float*)d_out, N);
}

// round 3
// speedup vs baseline: 2.4827x; 2.4827x over previous
#include <cuda_runtime.h>

#define NMAX 100000
#define EMAX 1600000
#define FIN  11
#define HDIM 128
#define DOUT 64
#define LNEPS 1e-5f
#define SCAN_BS 1024
#define MAXNB 128

// ---------------- scratch (static device globals; no runtime allocation) ----------------
__device__ int   g_rowptr[NMAX + 1];
__device__ int   g_cnt   [NMAX];        // counts, then reused as fill cursor
__device__ int   g_csr   [EMAX];        // source node id per CSR slot (grouped by target)
__device__ int   g_bsum  [MAXNB];
__device__ int   g_boff  [MAXNB];
__device__ float g_h0  [NMAX * HDIM];
__device__ float g_h1  [NMAX * HDIM];
__device__ float g_xt2 [NMAX * DOUT];

// ---------------- CSR build ----------------
__global__ void zero_cnt(int N) {
    int i = blockIdx.x * blockDim.x + threadIdx.x;
    if (i < N) g_cnt[i] = 0;
}

__global__ void count_edges(const int* __restrict__ ei, int E) {
    int e = blockIdx.x * blockDim.x + threadIdx.x;
    if (e < E) atomicAdd(&g_cnt[ei[E + e]], 1);
}

__global__ void scan_partial(int N) {
    __shared__ int sh[SCAN_BS];
    int t = threadIdx.x;
    int i = blockIdx.x * SCAN_BS + t;
    sh[t] = (i < N) ? g_cnt[i] : 0;
    __syncthreads();
    for (int off = SCAN_BS / 2; off; off >>= 1) {
        if (t < off) sh[t] += sh[t + off];
        __syncthreads();
    }
    if (t == 0) g_bsum[blockIdx.x] = sh[0];
}

__global__ void scan_bsums(int NB) {
    __shared__ int sh[MAXNB];
    int t = threadIdx.x;
    int v = (t < NB) ? g_bsum[t] : 0;
    sh[t] = v;
    __syncthreads();
    for (int off = 1; off < MAXNB; off <<= 1) {
        int x = (t >= off) ? sh[t - off] : 0;
        __syncthreads();
        sh[t] += x;
        __syncthreads();
    }
    if (t < NB) g_boff[t] = sh[t] - v;   // exclusive
}

__global__ void scan_final(int N, int E) {
    __shared__ int sh[SCAN_BS];
    int t = threadIdx.x;
    int i = blockIdx.x * SCAN_BS + t;
    int v = (i < N) ? g_cnt[i] : 0;
    sh[t] = v;
    __syncthreads();
    for (int off = 1; off < SCAN_BS; off <<= 1) {
        int x = (t >= off) ? sh[t - off] : 0;
        __syncthreads();
        sh[t] += x;
        __syncthreads();
    }
    if (i < N) {
        g_rowptr[i] = g_boff[blockIdx.x] + sh[t] - v;  // exclusive scan
        g_cnt[i] = 0;                                  // reset cursor for fill
    }
    if (i == 0) g_rowptr[N] = E;
}

__global__ void fill_csr(const int* __restrict__ ei, int E) {
    int e = blockIdx.x * blockDim.x + threadIdx.x;
    if (e >= E) return;
    int s = ei[e], t = ei[E + e];
    int pos = atomicAdd(&g_cnt[t], 1);
    g_csr[g_rowptr[t] + pos] = s;
}

// ---------------- conv0 (fused gather@11 + GEMM + LN + ReLU), warp per node ----------------
__global__ void conv0_fused(const float* __restrict__ nf,
                            const float* __restrict__ W0, const float* __restrict__ b0,
                            const float* __restrict__ g0, const float* __restrict__ be0, int N) {
    __shared__ float sW[HDIM * FIN];
    __shared__ float sb[HDIM], sg[HDIM], sbe[HDIM];
    for (int i = threadIdx.x; i < HDIM * FIN; i += blockDim.x) sW[i] = W0[i];
    for (int i = threadIdx.x; i < HDIM; i += blockDim.x) { sb[i] = b0[i]; sg[i] = g0[i]; sbe[i] = be0[i]; }
    __syncthreads();
    int lane   = threadIdx.x & 31;
    int gwarp  = (blockIdx.x * blockDim.x + threadIdx.x) >> 5;
    int nwarps = (gridDim.x * blockDim.x) >> 5;
    bool lv = lane < FIN;
    for (int node = gwarp; node < N; node += nwarps) {
        int rp0 = g_rowptr[node], rp1 = g_rowptr[node + 1];
        int deg = rp1 - rp0;
        float a = 0.f;
        int j = rp0;
        for (; j + 1 < rp1; j += 2) {
            int s0 = g_csr[j], s1 = g_csr[j + 1];
            float x0 = lv ? __ldg(nf + (long long)s0 * FIN + lane) : 0.f;
            float x1 = lv ? __ldg(nf + (long long)s1 * FIN + lane) : 0.f;
            a += x0 + x1;
        }
        if (j < rp1) {
            int s = g_csr[j];
            if (lv) a += __ldg(nf + (long long)s * FIN + lane);
        }
        float inv = deg > 0 ? 1.f / (float)deg : 0.f;
        a *= inv;
        float m[FIN];
#pragma unroll
        for (int i = 0; i < FIN; i++) m[i] = __shfl_sync(0xffffffffu, a, i);
        float mk = deg > 0 ? 1.f : 0.f;
        float v[4];
#pragma unroll
        for (int r = 0; r < 4; r++) {
            int jo = lane + 32 * r;
            float acc = sb[jo];
#pragma unroll
            for (int i = 0; i < FIN; i++) acc = fmaf(m[i], sW[jo * FIN + i], acc);
            v[r] = acc * mk;  // deg==0: reference conv output is exactly 0
        }
        float s  = v[0] + v[1] + v[2] + v[3];
        float s2 = v[0] * v[0] + v[1] * v[1] + v[2] * v[2] + v[3] * v[3];
#pragma unroll
        for (int o = 16; o; o >>= 1) {
            s  += __shfl_xor_sync(0xffffffffu, s,  o);
            s2 += __shfl_xor_sync(0xffffffffu, s2, o);
        }
        float mu  = s * (1.f / HDIM);
        float var = s2 * (1.f / HDIM) - mu * mu;
        float rs  = rsqrtf(var + LNEPS);
#pragma unroll
        for (int r = 0; r < 4; r++) {
            int jo = lane + 32 * r;
            float y = (v[r] - mu) * rs * sg[jo] + sbe[jo];
            g_h0[(long long)node * HDIM + jo] = fmaxf(y, 0.f);
        }
    }
}

// ---------------- conv1 (fused gather@128 + GEMM + LN + ReLU) ----------------
// W1 transposed into smem (pitch 132); 4 nodes per warp so W reads amortize.
#define W1PITCH 132
#define CONV1_SMEM ((HDIM * W1PITCH + 8 * 4 * HDIM + 3 * HDIM) * 4)
__global__ void conv1_fused(const float* __restrict__ W, const float* __restrict__ b,
                            const float* __restrict__ gg, const float* __restrict__ be, int N) {
    extern __shared__ float smem[];
    float* Wt  = smem;                    // [128][132]
    float* sM  = Wt + HDIM * W1PITCH;     // [8 warps][4 nodes * 128]
    float* sb  = sM + 8 * 4 * HDIM;
    float* sg  = sb + HDIM;
    float* sbe = sg + HDIM;
    int tid = threadIdx.x;
    for (int i = tid; i < HDIM * HDIM; i += blockDim.x) {
        int j = i >> 7, k = i & 127;      // W[j][k]
        Wt[k * W1PITCH + j] = W[i];
    }
    for (int i = tid; i < HDIM; i += blockDim.x) { sb[i] = b[i]; sg[i] = gg[i]; sbe[i] = be[i]; }
    __syncthreads();
    int warp = tid >> 5, lane = tid & 31;
    float* mw = sM + warp * 4 * HDIM;
    long long gwarp = blockIdx.x * 8 + warp;
    long long nw    = (long long)gridDim.x * 8;
    for (long long base = gwarp * 4; base < N; base += nw * 4) {
        __syncwarp();
        float msk[4];
#pragma unroll
        for (int q = 0; q < 4; q++) {
            long long node = base + q;
            float4 acc = make_float4(0.f, 0.f, 0.f, 0.f);
            float mk = 0.f;
            if (node < N) {
                int rp0 = g_rowptr[node], rp1 = g_rowptr[node + 1];
                int j = rp0;
                for (; j + 1 < rp1; j += 2) {
                    int s0 = g_csr[j], s1 = g_csr[j + 1];
                    float4 v0 = *(const float4*)(g_h0 + (long long)s0 * HDIM + lane * 4);
                    float4 v1 = *(const float4*)(g_h0 + (long long)s1 * HDIM + lane * 4);
                    acc.x += v0.x + v1.x; acc.y += v0.y + v1.y;
                    acc.z += v0.z + v1.z; acc.w += v0.w + v1.w;
                }
                if (j < rp1) {
                    int s = g_csr[j];
                    float4 v = *(const float4*)(g_h0 + (long long)s * HDIM + lane * 4);
                    acc.x += v.x; acc.y += v.y; acc.z += v.z; acc.w += v.w;
                }
                int deg = rp1 - rp0;
                float inv = deg > 0 ? 1.f / (float)deg : 0.f;
                mk = deg > 0 ? 1.f : 0.f;
                acc.x *= inv; acc.y *= inv; acc.z *= inv; acc.w *= inv;
            }
            msk[q] = mk;
            *(float4*)(mw + q * HDIM + lane * 4) = acc;
        }
        __syncwarp();
        float4 b4 = *(const float4*)&sb[lane * 4];
        float acc[4][4];
#pragma unroll
        for (int q = 0; q < 4; q++) { acc[q][0] = b4.x; acc[q][1] = b4.y; acc[q][2] = b4.z; acc[q][3] = b4.w; }
        for (int k = 0; k < HDIM; k += 4) {
            float4 w0 = *(const float4*)&Wt[(k + 0) * W1PITCH + lane * 4];
            float4 w1 = *(const float4*)&Wt[(k + 1) * W1PITCH + lane * 4];
            float4 w2 = *(const float4*)&Wt[(k + 2) * W1PITCH + lane * 4];
            float4 w3 = *(const float4*)&Wt[(k + 3) * W1PITCH + lane * 4];
#pragma unroll
            for (int q = 0; q < 4; q++) {
                float4 mq = *(const float4*)(mw + q * HDIM + k);   // warp-broadcast LDS.128
                acc[q][0] = fmaf(mq.x, w0.x, acc[q][0]); acc[q][1] = fmaf(mq.x, w0.y, acc[q][1]);
                acc[q][2] = fmaf(mq.x, w0.z, acc[q][2]); acc[q][3] = fmaf(mq.x, w0.w, acc[q][3]);
                acc[q][0] = fmaf(mq.y, w1.x, acc[q][0]); acc[q][1] = fmaf(mq.y, w1.y, acc[q][1]);
                acc[q][2] = fmaf(mq.y, w1.z, acc[q][2]); acc[q][3] = fmaf(mq.y, w1.w, acc[q][3]);
                acc[q][0] = fmaf(mq.z, w2.x, acc[q][0]); acc[q][1] = fmaf(mq.z, w2.y, acc[q][1]);
                acc[q][2] = fmaf(mq.z, w2.z, acc[q][2]); acc[q][3] = fmaf(mq.z, w2.w, acc[q][3]);
                acc[q][0] = fmaf(mq.w, w3.x, acc[q][0]); acc[q][1] = fmaf(mq.w, w3.y, acc[q][1]);
                acc[q][2] = fmaf(mq.w, w3.z, acc[q][2]); acc[q][3] = fmaf(mq.w, w3.w, acc[q][3]);
            }
        }
        float4 g4  = *(const float4*)&sg[lane * 4];
        float4 be4 = *(const float4*)&sbe[lane * 4];
#pragma unroll
        for (int q = 0; q < 4; q++) {
            if (base + q >= N) break;
            float v0 = acc[q][0] * msk[q], v1 = acc[q][1] * msk[q];
            float v2 = acc[q][2] * msk[q], v3 = acc[q][3] * msk[q];
            float s  = v0 + v1 + v2 + v3;
            float s2 = v0 * v0 + v1 * v1 + v2 * v2 + v3 * v3;
#pragma unroll
            for (int o = 16; o; o >>= 1) {
                s  += __shfl_xor_sync(0xffffffffu, s,  o);
                s2 += __shfl_xor_sync(0xffffffffu, s2, o);
            }
            float mu  = s * (1.f / HDIM);
            float var = s2 * (1.f / HDIM) - mu * mu;
            float rs  = rsqrtf(var + LNEPS);
            float4 o4;
            o4.x = fmaxf((v0 - mu) * rs * g4.x + be4.x, 0.f);
            o4.y = fmaxf((v1 - mu) * rs * g4.y + be4.y, 0.f);
            o4.z = fmaxf((v2 - mu) * rs * g4.z + be4.z, 0.f);
            o4.w = fmaxf((v3 - mu) * rs * g4.w + be4.w, 0.f);
            *(float4*)(g_h1 + (base + q) * HDIM + lane * 4) = o4;
        }
    }
}

// ---------------- gemm2: xt2 = h1 @ W2^T + b2  (128 -> 64) ----------------
#define W2PITCH 66
#define GEMM2_SMEM ((HDIM * W2PITCH + 8 * 4 * HDIM + DOUT) * 4)
__global__ void gemm2_kernel(const float* __restrict__ W, const float* __restrict__ b, int N) {
    extern __shared__ float smem[];
    float* Wt = smem;                   // [128][66], 64 outputs
    float* sM = Wt + HDIM * W2PITCH;
    float* sb = sM + 8 * 4 * HDIM;
    int tid = threadIdx.x;
    for (int i = tid; i < DOUT * HDIM; i += blockDim.x) {
        int j = i >> 7, k = i & 127;    // W2[j][k], j < 64
        Wt[k * W2PITCH + j] = W[i];
    }
    for (int i = tid; i < DOUT; i += blockDim.x) sb[i] = b[i];
    __syncthreads();
    int warp = tid >> 5, lane = tid & 31;
    float* mw = sM + warp * 4 * HDIM;
    long long gwarp = blockIdx.x * 8 + warp;
    long long nw    = (long long)gridDim.x * 8;
    for (long long base = gwarp * 4; base < N; base += nw * 4) {
        __syncwarp();
#pragma unroll
        for (int q = 0; q < 4; q++) {
            long long node = base + q;
            float4 v = make_float4(0.f, 0.f, 0.f, 0.f);
            if (node < N) v = *(const float4*)(g_h1 + node * HDIM + lane * 4);
            *(float4*)(mw + q * HDIM + lane * 4) = v;
        }
        __syncwarp();
        float2 b2v = *(const float2*)&sb[lane * 2];
        float acc[4][2];
#pragma unroll
        for (int q = 0; q < 4; q++) { acc[q][0] = b2v.x; acc[q][1] = b2v.y; }
        for (int k = 0; k < HDIM; k += 4) {
            float2 w0 = *(const float2*)&Wt[(k + 0) * W2PITCH + lane * 2];
            float2 w1 = *(const float2*)&Wt[(k + 1) * W2PITCH + lane * 2];
            float2 w2 = *(const float2*)&Wt[(k + 2) * W2PITCH + lane * 2];
            float2 w3 = *(const float2*)&Wt[(k + 3) * W2PITCH + lane * 2];
#pragma unroll
            for (int q = 0; q < 4; q++) {
                float4 mq = *(const float4*)(mw + q * HDIM + k);
                acc[q][0] = fmaf(mq.x, w0.x, acc[q][0]); acc[q][1] = fmaf(mq.x, w0.y, acc[q][1]);
                acc[q][0] = fmaf(mq.y, w1.x, acc[q][0]); acc[q][1] = fmaf(mq.y, w1.y, acc[q][1]);
                acc[q][0] = fmaf(mq.z, w2.x, acc[q][0]); acc[q][1] = fmaf(mq.z, w2.y, acc[q][1]);
                acc[q][0] = fmaf(mq.w, w3.x, acc[q][0]); acc[q][1] = fmaf(mq.w, w3.y, acc[q][1]);
            }
        }
#pragma unroll
        for (int q = 0; q < 4; q++) {
            if (base + q >= N) break;
            float2 o; o.x = acc[q][0]; o.y = acc[q][1];
            *(float2*)(g_xt2 + (base + q) * DOUT + lane * 2) = o;
        }
    }
}

// ---------------- final (fused gather@64 + LN), warp per node ----------------
__global__ void final_fused(const float* __restrict__ g2, const float* __restrict__ be2,
                            float* __restrict__ out, int N) {
    int lane   = threadIdx.x & 31;
    int gwarp  = (blockIdx.x * blockDim.x + threadIdx.x) >> 5;
    int nwarps = (gridDim.x * blockDim.x) >> 5;
    float gA = g2[lane * 2], gB = g2[lane * 2 + 1];
    float bA = be2[lane * 2], bB = be2[lane * 2 + 1];
    for (int node = gwarp; node < N; node += nwarps) {
        int rp0 = g_rowptr[node], rp1 = g_rowptr[node + 1];
        int deg = rp1 - rp0;
        float2 acc = make_float2(0.f, 0.f);
        int j = rp0;
        for (; j + 1 < rp1; j += 2) {
            int s0 = g_csr[j], s1 = g_csr[j + 1];
            float2 v0 = *(const float2*)(g_xt2 + (long long)s0 * DOUT + lane * 2);
            float2 v1 = *(const float2*)(g_xt2 + (long long)s1 * DOUT + lane * 2);
            acc.x += v0.x + v1.x; acc.y += v0.y + v1.y;
        }
        if (j < rp1) {
            int s = g_csr[j];
            float2 v = *(const float2*)(g_xt2 + (long long)s * DOUT + lane * 2);
            acc.x += v.x; acc.y += v.y;
        }
        float inv = deg > 0 ? 1.f / (float)deg : 1.f;  // reference: deg==0 -> agg 0 / 1
        acc.x *= inv; acc.y *= inv;
        float s  = acc.x + acc.y;
        float s2 = acc.x * acc.x + acc.y * acc.y;
#pragma unroll
        for (int o = 16; o; o >>= 1) {
            s  += __shfl_xor_sync(0xffffffffu, s,  o);
            s2 += __shfl_xor_sync(0xffffffffu, s2, o);
        }
        float mu  = s * (1.f / DOUT);
        float var = s2 * (1.f / DOUT) - mu * mu;
        float rs  = rsqrtf(var + LNEPS);
        float2 o2;
        o2.x = (acc.x - mu) * rs * gA + bA;
        o2.y = (acc.y - mu) * rs * gB + bB;
        *(float2*)(out + (long long)node * DOUT + lane * 2) = o2;
    }
}

// ---------------- launch ----------------
extern "C" void kernel_launch(void* const* d_in, const int* in_sizes, int n_in,
                              void* d_out, int out_size) {
    const float* nf  = (const float*)d_in[0];
    const int*   ei  = (const int*)d_in[1];
    const float* W0  = (const float*)d_in[2];
    const float* b0  = (const float*)d_in[3];
    const float* W1  = (const float*)d_in[4];
    const float* b1  = (const float*)d_in[5];
    const float* W2  = (const float*)d_in[6];
    const float* b2  = (const float*)d_in[7];
    const float* g0  = (const float*)d_in[8];
    const float* be0 = (const float*)d_in[9];
    const float* g1  = (const float*)d_in[10];
    const float* be1 = (const float*)d_in[11];
    const float* g2  = (const float*)d_in[12];
    const float* be2 = (const float*)d_in[13];
    int N = in_sizes[0] / FIN;
    int E = in_sizes[1] / 2;
    int NB = (N + SCAN_BS - 1) / SCAN_BS;

    cudaFuncSetAttribute(conv1_fused,  cudaFuncAttributeMaxDynamicSharedMemorySize, CONV1_SMEM);
    cudaFuncSetAttribute(gemm2_kernel, cudaFuncAttributeMaxDynamicSharedMemorySize, GEMM2_SMEM);

    // CSR build (incoming edges grouped by target)
    zero_cnt<<<(N + 255) / 256, 256>>>(N);
    count_edges<<<(E + 255) / 256, 256>>>(ei, E);
    scan_partial<<<NB, SCAN_BS>>>(N);
    scan_bsums<<<1, MAXNB>>>(NB);
    scan_final<<<NB, SCAN_BS>>>(N, E);
    fill_csr<<<(E + 255) / 256, 256>>>(ei, E);

    // layers (all aggregation is CSR gather, zero float atomics)
    conv0_fused<<<1480, 256>>>(nf, W0, b0, g0, be0, N);
    conv1_fused<<<1480, 256, CONV1_SMEM>>>(W1, b1, g1, be1, N);
    gemm2_kernel<<<1480, 256, GEMM2_SMEM>>>(W2, b2, N);
    final_fused<<<1480, 256>>>(g2, be2, (float*)d_out, N);
}

// round 4
// speedup vs baseline: 2.8875x; 1.1631x over previous
#include <cuda_runtime.h>
#include <cuda_fp16.h>

#define NMAX 100000
#define EMAX 1600000
#define FIN  11
#define HDIM 128
#define DOUT 64
#define LNEPS 1e-5f
#define SCAN_BS 1024
#define MAXNB 128

// ---------------- scratch (static device globals; no runtime allocation) ----------------
__device__ int   g_rowptr[NMAX + 1];
__device__ int   g_cnt   [NMAX];
__device__ int   g_csr   [EMAX];
__device__ int   g_bsum  [MAXNB];
__device__ int   g_boff  [MAXNB];
__device__ uint2    g_h0h [NMAX * 32];   // h0 in fp16: 128 halves/row = 32 uint2
__device__ unsigned g_xt2h[NMAX * 32];   // xt2 in fp16: 64 halves/row = 32 half2

// ---------------- f32x2 packed-FMA helpers (sm_103a) ----------------
__device__ __forceinline__ unsigned long long pack2(float lo, float hi) {
    unsigned long long r;
    asm("mov.b64 %0, {%1, %2};" : "=l"(r) : "f"(lo), "f"(hi));
    return r;
}
__device__ __forceinline__ void fma2(unsigned long long& d, unsigned long long a, unsigned long long b) {
    asm("fma.rn.f32x2 %0, %1, %2, %0;" : "+l"(d) : "l"(a), "l"(b));
}
__device__ __forceinline__ float2 unpack2(unsigned long long v) {
    float2 f;
    asm("mov.b64 {%0, %1}, %2;" : "=f"(f.x), "=f"(f.y) : "l"(v));
    return f;
}
__device__ __forceinline__ void add_h4(float4& a, uint2 r) {
    float2 lo = __half22float2(*(__half2*)&r.x);
    float2 hi = __half22float2(*(__half2*)&r.y);
    a.x += lo.x; a.y += lo.y; a.z += hi.x; a.w += hi.y;
}

// ---------------- CSR build ----------------
__global__ void zero_cnt(int N) {
    int i = blockIdx.x * blockDim.x + threadIdx.x;
    if (i < N) g_cnt[i] = 0;
}
__global__ void count_edges(const int* __restrict__ ei, int E) {
    int e = blockIdx.x * blockDim.x + threadIdx.x;
    if (e < E) atomicAdd(&g_cnt[ei[E + e]], 1);
}
__global__ void scan_partial(int N) {
    __shared__ int sh[SCAN_BS];
    int t = threadIdx.x;
    int i = blockIdx.x * SCAN_BS + t;
    sh[t] = (i < N) ? g_cnt[i] : 0;
    __syncthreads();
    for (int off = SCAN_BS / 2; off; off >>= 1) {
        if (t < off) sh[t] += sh[t + off];
        __syncthreads();
    }
    if (t == 0) g_bsum[blockIdx.x] = sh[0];
}
__global__ void scan_bsums(int NB) {
    __shared__ int sh[MAXNB];
    int t = threadIdx.x;
    int v = (t < NB) ? g_bsum[t] : 0;
    sh[t] = v;
    __syncthreads();
    for (int off = 1; off < MAXNB; off <<= 1) {
        int x = (t >= off) ? sh[t - off] : 0;
        __syncthreads();
        sh[t] += x;
        __syncthreads();
    }
    if (t < NB) g_boff[t] = sh[t] - v;
}
__global__ void scan_final(int N, int E) {
    __shared__ int sh[SCAN_BS];
    int t = threadIdx.x;
    int i = blockIdx.x * SCAN_BS + t;
    int v = (i < N) ? g_cnt[i] : 0;
    sh[t] = v;
    __syncthreads();
    for (int off = 1; off < SCAN_BS; off <<= 1) {
        int x = (t >= off) ? sh[t - off] : 0;
        __syncthreads();
        sh[t] += x;
        __syncthreads();
    }
    if (i < N) {
        g_rowptr[i] = g_boff[blockIdx.x] + sh[t] - v;
        g_cnt[i] = 0;
    }
    if (i == 0) g_rowptr[N] = E;
}
__global__ void fill_csr(const int* __restrict__ ei, int E) {
    int e = blockIdx.x * blockDim.x + threadIdx.x;
    if (e >= E) return;
    int s = ei[e], t = ei[E + e];
    int pos = atomicAdd(&g_cnt[t], 1);
    g_csr[g_rowptr[t] + pos] = s;
}

// ---------------- conv0: gather@11 + GEMM + LN + ReLU -> h0 (fp16), warp per node ----------------
__global__ void conv0_fused(const float* __restrict__ nf,
                            const float* __restrict__ W0, const float* __restrict__ b0,
                            const float* __restrict__ g0, const float* __restrict__ be0, int N) {
    __shared__ __align__(16) float sWt[FIN * HDIM];   // [i][j] : W0 transposed
    __shared__ __align__(16) float sb[HDIM], sg[HDIM], sbe[HDIM];
    for (int idx = threadIdx.x; idx < FIN * HDIM; idx += blockDim.x) {
        int i = idx >> 7, j = idx & 127;
        sWt[i * HDIM + j] = W0[j * FIN + i];
    }
    for (int i = threadIdx.x; i < HDIM; i += blockDim.x) { sb[i] = b0[i]; sg[i] = g0[i]; sbe[i] = be0[i]; }
    __syncthreads();
    int lane   = threadIdx.x & 31;
    int gwarp  = (blockIdx.x * blockDim.x + threadIdx.x) >> 5;
    int nwarps = (gridDim.x * blockDim.x) >> 5;
    bool lv = lane < FIN;
    for (int node = gwarp; node < N; node += nwarps) {
        int rp0 = g_rowptr[node], rp1 = g_rowptr[node + 1];
        int deg = rp1 - rp0;
        float a = 0.f;
        int j = rp0;
        for (; j + 3 < rp1; j += 4) {
            int s0 = g_csr[j], s1 = g_csr[j + 1], s2 = g_csr[j + 2], s3 = g_csr[j + 3];
            float x0 = lv ? __ldg(nf + (long long)s0 * FIN + lane) : 0.f;
            float x1 = lv ? __ldg(nf + (long long)s1 * FIN + lane) : 0.f;
            float x2 = lv ? __ldg(nf + (long long)s2 * FIN + lane) : 0.f;
            float x3 = lv ? __ldg(nf + (long long)s3 * FIN + lane) : 0.f;
            a += (x0 + x1) + (x2 + x3);
        }
        for (; j < rp1; j++) {
            int s = g_csr[j];
            if (lv) a += __ldg(nf + (long long)s * FIN + lane);
        }
        float inv = deg > 0 ? 1.f / (float)deg : 0.f;
        a *= inv;
        float m[FIN];
#pragma unroll
        for (int i = 0; i < FIN; i++) m[i] = __shfl_sync(0xffffffffu, a, i);
        float mk = deg > 0 ? 1.f : 0.f;
        float4 vv = *(const float4*)&sb[lane * 4];
#pragma unroll
        for (int i = 0; i < FIN; i++) {
            float4 w = *(const float4*)&sWt[i * HDIM + lane * 4];
            vv.x = fmaf(m[i], w.x, vv.x); vv.y = fmaf(m[i], w.y, vv.y);
            vv.z = fmaf(m[i], w.z, vv.z); vv.w = fmaf(m[i], w.w, vv.w);
        }
        vv.x *= mk; vv.y *= mk; vv.z *= mk; vv.w *= mk;   // deg==0: conv output exactly 0
        float s  = vv.x + vv.y + vv.z + vv.w;
        float s2 = vv.x * vv.x + vv.y * vv.y + vv.z * vv.z + vv.w * vv.w;
#pragma unroll
        for (int o = 16; o; o >>= 1) {
            s  += __shfl_xor_sync(0xffffffffu, s,  o);
            s2 += __shfl_xor_sync(0xffffffffu, s2, o);
        }
        float mu  = s * (1.f / HDIM);
        float var = s2 * (1.f / HDIM) - mu * mu;
        float rs  = rsqrtf(var + LNEPS);
        float4 g4  = *(const float4*)&sg[lane * 4];
        float4 be4 = *(const float4*)&sbe[lane * 4];
        float y0 = fmaxf((vv.x - mu) * rs * g4.x + be4.x, 0.f);
        float y1 = fmaxf((vv.y - mu) * rs * g4.y + be4.y, 0.f);
        float y2 = fmaxf((vv.z - mu) * rs * g4.z + be4.z, 0.f);
        float y3 = fmaxf((vv.w - mu) * rs * g4.w + be4.w, 0.f);
        __half2 hA = __float22half2_rn(make_float2(y0, y1));
        __half2 hB = __float22half2_rn(make_float2(y2, y3));
        uint2 u; u.x = *(unsigned*)&hA; u.y = *(unsigned*)&hB;
        g_h0h[(size_t)node * 32 + lane] = u;
    }
}

// ---------------- conv1+gemm2 fused: gather h0(fp16) -> GEMM1(f32x2) -> LN+ReLU -> GEMM2(f32x2) -> xt2(fp16) ----------------
#define W1PITCH 132
#define W2PITCH 66
#define C1_WARPS 16
#define C1_THREADS (C1_WARPS * 32)
#define CONV1_SMEM ((HDIM * W1PITCH + HDIM * W2PITCH + C1_WARPS * 4 * HDIM + 3 * HDIM + DOUT) * 4)

__global__ void __launch_bounds__(C1_THREADS, 1) conv1gemm2_fused(
    const float* __restrict__ W1, const float* __restrict__ b1,
    const float* __restrict__ g1, const float* __restrict__ be1,
    const float* __restrict__ W2, const float* __restrict__ b2, int N)
{
    extern __shared__ float smem[];
    float* Wt  = smem;                         // [128][132]  (W1 transposed)
    float* Wt2 = Wt  + HDIM * W1PITCH;         // [128][66]   (W2 transposed)
    float* sM  = Wt2 + HDIM * W2PITCH;         // [16 warps][4 nodes * 128]
    float* sb  = sM  + C1_WARPS * 4 * HDIM;
    float* sg  = sb  + HDIM;
    float* sbe = sg  + HDIM;
    float* sb2 = sbe + HDIM;
    int tid = threadIdx.x;
    for (int i = tid; i < HDIM * HDIM; i += C1_THREADS) {
        int j = i >> 7, k = i & 127;
        Wt[k * W1PITCH + j] = W1[i];
    }
    for (int i = tid; i < DOUT * HDIM; i += C1_THREADS) {
        int j = i >> 7, k = i & 127;
        Wt2[k * W2PITCH + j] = W2[i];
    }
    for (int i = tid; i < HDIM; i += C1_THREADS) { sb[i] = b1[i]; sg[i] = g1[i]; sbe[i] = be1[i]; }
    for (int i = tid; i < DOUT; i += C1_THREADS) sb2[i] = b2[i];
    __syncthreads();

    int warp = tid >> 5, lane = tid & 31;
    float* mw = sM + warp * 4 * HDIM;
    long long stride = (long long)gridDim.x * C1_WARPS * 4;
    for (long long base = (long long)(blockIdx.x * C1_WARPS + warp) * 4; base < N; base += stride) {
        __syncwarp();
        float msk[4];
#pragma unroll
        for (int q = 0; q < 4; q++) {
            long long node = base + q;
            float4 acc = make_float4(0.f, 0.f, 0.f, 0.f);
            float mk = 0.f;
            if (node < N) {
                int rp0 = g_rowptr[node], rp1 = g_rowptr[node + 1];
                int j = rp0;
                for (; j + 3 < rp1; j += 4) {
                    uint2 r0 = g_h0h[(size_t)g_csr[j]     * 32 + lane];
                    uint2 r1 = g_h0h[(size_t)g_csr[j + 1] * 32 + lane];
                    uint2 r2 = g_h0h[(size_t)g_csr[j + 2] * 32 + lane];
                    uint2 r3 = g_h0h[(size_t)g_csr[j + 3] * 32 + lane];
                    add_h4(acc, r0); add_h4(acc, r1); add_h4(acc, r2); add_h4(acc, r3);
                }
                for (; j < rp1; j++) {
                    uint2 r = g_h0h[(size_t)g_csr[j] * 32 + lane];
                    add_h4(acc, r);
                }
                int deg = rp1 - rp0;
                float inv = deg > 0 ? 1.f / (float)deg : 0.f;
                mk = deg > 0 ? 1.f : 0.f;
                acc.x *= inv; acc.y *= inv; acc.z *= inv; acc.w *= inv;
            }
            msk[q] = mk;
            *(float4*)(mw + q * HDIM + lane * 4) = acc;
        }
        __syncwarp();

        // ---- GEMM1: 128->128, f32x2 packed FMA, 4 nodes/warp ----
        unsigned long long a01[4], a23[4];
        unsigned long long bias01 = *(const unsigned long long*)&sb[lane * 4];
        unsigned long long bias23 = *(const unsigned long long*)&sb[lane * 4 + 2];
#pragma unroll
        for (int q = 0; q < 4; q++) { a01[q] = bias01; a23[q] = bias23; }
        for (int k = 0; k < HDIM; k += 4) {
            ulonglong2 w0 = *(const ulonglong2*)&Wt[(k + 0) * W1PITCH + lane * 4];
            ulonglong2 w1 = *(const ulonglong2*)&Wt[(k + 1) * W1PITCH + lane * 4];
            ulonglong2 w2 = *(const ulonglong2*)&Wt[(k + 2) * W1PITCH + lane * 4];
            ulonglong2 w3 = *(const ulonglong2*)&Wt[(k + 3) * W1PITCH + lane * 4];
#pragma unroll
            for (int q = 0; q < 4; q++) {
                float4 mq = *(const float4*)(mw + q * HDIM + k);
                unsigned long long p;
                p = pack2(mq.x, mq.x); fma2(a01[q], p, w0.x); fma2(a23[q], p, w0.y);
                p = pack2(mq.y, mq.y); fma2(a01[q], p, w1.x); fma2(a23[q], p, w1.y);
                p = pack2(mq.z, mq.z); fma2(a01[q], p, w2.x); fma2(a23[q], p, w2.y);
                p = pack2(mq.w, mq.w); fma2(a01[q], p, w3.x); fma2(a23[q], p, w3.y);
            }
        }

        // ---- LN + ReLU, write h1 back to mw ----
        float4 g4  = *(const float4*)&sg[lane * 4];
        float4 be4 = *(const float4*)&sbe[lane * 4];
#pragma unroll
        for (int q = 0; q < 4; q++) {
            if (base + q < N) {
                float2 p01 = unpack2(a01[q]), p23 = unpack2(a23[q]);
                float v0 = p01.x * msk[q], v1 = p01.y * msk[q];
                float v2 = p23.x * msk[q], v3 = p23.y * msk[q];
                float s  = v0 + v1 + v2 + v3;
                float s2 = v0 * v0 + v1 * v1 + v2 * v2 + v3 * v3;
#pragma unroll
                for (int o = 16; o; o >>= 1) {
                    s  += __shfl_xor_sync(0xffffffffu, s,  o);
                    s2 += __shfl_xor_sync(0xffffffffu, s2, o);
                }
                float mu  = s * (1.f / HDIM);
                float var = s2 * (1.f / HDIM) - mu * mu;
                float rs  = rsqrtf(var + LNEPS);
                float4 o4;
                o4.x = fmaxf((v0 - mu) * rs * g4.x + be4.x, 0.f);
                o4.y = fmaxf((v1 - mu) * rs * g4.y + be4.y, 0.f);
                o4.z = fmaxf((v2 - mu) * rs * g4.z + be4.z, 0.f);
                o4.w = fmaxf((v3 - mu) * rs * g4.w + be4.w, 0.f);
                *(float4*)(mw + q * HDIM + lane * 4) = o4;
            }
        }
        __syncwarp();

        // ---- GEMM2: 128->64, f32x2 packed FMA, output fp16 ----
        unsigned long long c2[4];
        unsigned long long bias2 = *(const unsigned long long*)&sb2[lane * 2];
#pragma unroll
        for (int q = 0; q < 4; q++) c2[q] = bias2;
        for (int k = 0; k < HDIM; k += 4) {
            unsigned long long w0 = *(const unsigned long long*)&Wt2[(k + 0) * W2PITCH + lane * 2];
            unsigned long long w1 = *(const unsigned long long*)&Wt2[(k + 1) * W2PITCH + lane * 2];
            unsigned long long w2 = *(const unsigned long long*)&Wt2[(k + 2) * W2PITCH + lane * 2];
            unsigned long long w3 = *(const unsigned long long*)&Wt2[(k + 3) * W2PITCH + lane * 2];
#pragma unroll
            for (int q = 0; q < 4; q++) {
                float4 mq = *(const float4*)(mw + q * HDIM + k);
                unsigned long long p;
                p = pack2(mq.x, mq.x); fma2(c2[q], p, w0);
                p = pack2(mq.y, mq.y); fma2(c2[q], p, w1);
                p = pack2(mq.z, mq.z); fma2(c2[q], p, w2);
                p = pack2(mq.w, mq.w); fma2(c2[q], p, w3);
            }
        }
#pragma unroll
        for (int q = 0; q < 4; q++) {
            if (base + q >= N) break;
            float2 r = unpack2(c2[q]);
            __half2 h = __float22half2_rn(r);
            g_xt2h[(size_t)(base + q) * 32 + lane] = *(unsigned*)&h;
        }
    }
}

// ---------------- final: gather xt2(fp16) -> LN -> out, warp per node ----------------
__global__ void final_fused(const float* __restrict__ g2, const float* __restrict__ be2,
                            float* __restrict__ out, int N) {
    int lane   = threadIdx.x & 31;
    int gwarp  = (blockIdx.x * blockDim.x + threadIdx.x) >> 5;
    int nwarps = (gridDim.x * blockDim.x) >> 5;
    float gA = g2[lane * 2], gB = g2[lane * 2 + 1];
    float bA = be2[lane * 2], bB = be2[lane * 2 + 1];
    for (int node = gwarp; node < N; node += nwarps) {
        int rp0 = g_rowptr[node], rp1 = g_rowptr[node + 1];
        int deg = rp1 - rp0;
        float2 acc = make_float2(0.f, 0.f);
        int j = rp0;
        for (; j + 3 < rp1; j += 4) {
            unsigned r0 = g_xt2h[(size_t)g_csr[j]     * 32 + lane];
            unsigned r1 = g_xt2h[(size_t)g_csr[j + 1] * 32 + lane];
            unsigned r2 = g_xt2h[(size_t)g_csr[j + 2] * 32 + lane];
            unsigned r3 = g_xt2h[(size_t)g_csr[j + 3] * 32 + lane];
            float2 v0 = __half22float2(*(__half2*)&r0);
            float2 v1 = __half22float2(*(__half2*)&r1);
            float2 v2 = __half22float2(*(__half2*)&r2);
            float2 v3 = __half22float2(*(__half2*)&r3);
            acc.x += (v0.x + v1.x) + (v2.x + v3.x);
            acc.y += (v0.y + v1.y) + (v2.y + v3.y);
        }
        for (; j < rp1; j++) {
            unsigned r = g_xt2h[(size_t)g_csr[j] * 32 + lane];
            float2 v = __half22float2(*(__half2*)&r);
            acc.x += v.x; acc.y += v.y;
        }
        float inv = deg > 0 ? 1.f / (float)deg : 1.f;  // reference: deg==0 -> agg 0 / 1
        acc.x *= inv; acc.y *= inv;
        float s  = acc.x + acc.y;
        float s2 = acc.x * acc.x + acc.y * acc.y;
#pragma unroll
        for (int o = 16; o; o >>= 1) {
            s  += __shfl_xor_sync(0xffffffffu, s,  o);
            s2 += __shfl_xor_sync(0xffffffffu, s2, o);
        }
        float mu  = s * (1.f / DOUT);
        float var = s2 * (1.f / DOUT) - mu * mu;
        float rs  = rsqrtf(var + LNEPS);
        float2 o2;
        o2.x = (acc.x - mu) * rs * gA + bA;
        o2.y = (acc.y - mu) * rs * gB + bB;
        *(float2*)(out + (long long)node * DOUT + lane * 2) = o2;
    }
}

// ---------------- launch ----------------
extern "C" void kernel_launch(void* const* d_in, const int* in_sizes, int n_in,
                              void* d_out, int out_size) {
    const float* nf  = (const float*)d_in[0];
    const int*   ei  = (const int*)d_in[1];
    const float* W0  = (const float*)d_in[2];
    const float* b0  = (const float*)d_in[3];
    const float* W1  = (const float*)d_in[4];
    const float* b1  = (const float*)d_in[5];
    const float* W2  = (const float*)d_in[6];
    const float* b2  = (const float*)d_in[7];
    const float* g0  = (const float*)d_in[8];
    const float* be0 = (const float*)d_in[9];
    const float* g1  = (const float*)d_in[10];
    const float* be1 = (const float*)d_in[11];
    const float* g2  = (const float*)d_in[12];
    const float* be2 = (const float*)d_in[13];
    int N = in_sizes[0] / FIN;
    int E = in_sizes[1] / 2;
    int NB = (N + SCAN_BS - 1) / SCAN_BS;

    cudaFuncSetAttribute(conv1gemm2_fused, cudaFuncAttributeMaxDynamicSharedMemorySize, CONV1_SMEM);

    // CSR build (incoming edges grouped by target)
    zero_cnt<<<(N + 255) / 256, 256>>>(N);
    count_edges<<<(E + 255) / 256, 256>>>(ei, E);
    scan_partial<<<NB, SCAN_BS>>>(N);
    scan_bsums<<<1, MAXNB>>>(NB);
    scan_final<<<NB, SCAN_BS>>>(N, E);
    fill_csr<<<(E + 255) / 256, 256>>>(ei, E);

    // layers
    conv0_fused<<<1480, 256>>>(nf, W0, b0, g0, be0, N);
    conv1gemm2_fused<<<152, C1_THREADS, CONV1_SMEM>>>(W1, b1, g1, be1, W2, b2, N);
    final_fused<<<1480, 256>>>(g2, be2, (float*)d_out, N);
}

// round 9
// speedup vs baseline: 3.9389x; 1.3641x over previous
#include <cuda_runtime.h>
#include <cuda_fp16.h>

#define NMAX 100000
#define EMAX 1600000
#define FIN  11
#define HDIM 128
#define DOUT 64
#define LNEPS 1e-5f
#define SCAN_BS 1024
#define MAXNB 128

// ---------------- scratch (static device globals; no runtime allocation) ----------------
__device__ int   g_rowptr[NMAX + 1];
__device__ int   g_cnt   [NMAX];
__device__ int   g_csr   [EMAX];
__device__ int   g_bsum  [MAXNB];
__device__ int   g_boff  [MAXNB];
__device__ uint2    g_h0h [NMAX * 32];   // h0 in fp16: 128 halves/row = 32 uint2
__device__ unsigned g_xt2h[NMAX * 32];   // xt2 in fp16: 64 halves/row = 32 half2

__device__ __forceinline__ void add_h4(float4& a, uint2 r) {
    float2 lo = __half22float2(*(__half2*)&r.x);
    float2 hi = __half22float2(*(__half2*)&r.y);
    a.x += lo.x; a.y += lo.y; a.z += hi.x; a.w += hi.y;
}

// ---------------- mma helpers ----------------
__device__ __forceinline__ void ldm_x4(unsigned& a0, unsigned& a1, unsigned& a2, unsigned& a3, unsigned addr) {
    asm volatile("ldmatrix.sync.aligned.m8n8.x4.shared.b16 {%0,%1,%2,%3}, [%4];"
                 : "=r"(a0), "=r"(a1), "=r"(a2), "=r"(a3) : "r"(addr));
}
// B stored [n][k] row-major is already K-major ("col-major B") -> NON-trans ldmatrix
__device__ __forceinline__ void ldm_x2(unsigned& b0, unsigned& b1, unsigned addr) {
    asm volatile("ldmatrix.sync.aligned.m8n8.x2.shared.b16 {%0,%1}, [%2];"
                 : "=r"(b0), "=r"(b1) : "r"(addr));
}
__device__ __forceinline__ void mma16816(float* c, unsigned a0, unsigned a1, unsigned a2, unsigned a3,
                                         unsigned b0, unsigned b1) {
    asm volatile("mma.sync.aligned.m16n8k16.row.col.f32.f16.f16.f32 "
                 "{%0,%1,%2,%3}, {%4,%5,%6,%7}, {%8,%9}, {%0,%1,%2,%3};"
                 : "+f"(c[0]), "+f"(c[1]), "+f"(c[2]), "+f"(c[3])
                 : "r"(a0), "r"(a1), "r"(a2), "r"(a3), "r"(b0), "r"(b1));
}

// ---------------- CSR build ----------------
__global__ void zero_cnt(int N) {
    int i = blockIdx.x * blockDim.x + threadIdx.x;
    if (i < N) g_cnt[i] = 0;
}
__global__ void count_edges(const int* __restrict__ ei, int E) {
    int e = blockIdx.x * blockDim.x + threadIdx.x;
    if (e < E) atomicAdd(&g_cnt[ei[E + e]], 1);
}
__global__ void scan_partial(int N) {
    __shared__ int sh[SCAN_BS];
    int t = threadIdx.x;
    int i = blockIdx.x * SCAN_BS + t;
    sh[t] = (i < N) ? g_cnt[i] : 0;
    __syncthreads();
    for (int off = SCAN_BS / 2; off; off >>= 1) {
        if (t < off) sh[t] += sh[t + off];
        __syncthreads();
    }
    if (t == 0) g_bsum[blockIdx.x] = sh[0];
}
__global__ void scan_bsums(int NB) {
    __shared__ int sh[MAXNB];
    int t = threadIdx.x;
    int v = (t < NB) ? g_bsum[t] : 0;
    sh[t] = v;
    __syncthreads();
    for (int off = 1; off < MAXNB; off <<= 1) {
        int x = (t >= off) ? sh[t - off] : 0;
        __syncthreads();
        sh[t] += x;
        __syncthreads();
    }
    if (t < NB) g_boff[t] = sh[t] - v;
}
__global__ void scan_final(int N, int E) {
    __shared__ int sh[SCAN_BS];
    int t = threadIdx.x;
    int i = blockIdx.x * SCAN_BS + t;
    int v = (i < N) ? g_cnt[i] : 0;
    sh[t] = v;
    __syncthreads();
    for (int off = 1; off < SCAN_BS; off <<= 1) {
        int x = (t >= off) ? sh[t - off] : 0;
        __syncthreads();
        sh[t] += x;
        __syncthreads();
    }
    if (i < N) {
        g_rowptr[i] = g_boff[blockIdx.x] + sh[t] - v;
        g_cnt[i] = 0;
    }
    if (i == 0) g_rowptr[N] = E;
}
__global__ void fill_csr(const int* __restrict__ ei, int E) {
    int e = blockIdx.x * blockDim.x + threadIdx.x;
    if (e >= E) return;
    int s = ei[e], t = ei[E + e];
    int pos = atomicAdd(&g_cnt[t], 1);
    g_csr[g_rowptr[t] + pos] = s;
}

// ---------------- conv0: gather@11 + GEMM + LN + ReLU -> h0 (fp16), warp per node ----------------
__global__ void conv0_fused(const float* __restrict__ nf,
                            const float* __restrict__ W0, const float* __restrict__ b0,
                            const float* __restrict__ g0, const float* __restrict__ be0, int N) {
    __shared__ __align__(16) float sWt[FIN * HDIM];
    __shared__ __align__(16) float sb[HDIM], sg[HDIM], sbe[HDIM];
    for (int idx = threadIdx.x; idx < FIN * HDIM; idx += blockDim.x) {
        int i = idx >> 7, j = idx & 127;
        sWt[i * HDIM + j] = W0[j * FIN + i];
    }
    for (int i = threadIdx.x; i < HDIM; i += blockDim.x) { sb[i] = b0[i]; sg[i] = g0[i]; sbe[i] = be0[i]; }
    __syncthreads();
    int lane   = threadIdx.x & 31;
    int gwarp  = (blockIdx.x * blockDim.x + threadIdx.x) >> 5;
    int nwarps = (gridDim.x * blockDim.x) >> 5;
    bool lv = lane < FIN;
    for (int node = gwarp; node < N; node += nwarps) {
        int rp0 = g_rowptr[node], rp1 = g_rowptr[node + 1];
        int deg = rp1 - rp0;
        float a = 0.f;
        int j = rp0;
        for (; j + 3 < rp1; j += 4) {
            int s0 = g_csr[j], s1 = g_csr[j + 1], s2 = g_csr[j + 2], s3 = g_csr[j + 3];
            float x0 = lv ? __ldg(nf + (long long)s0 * FIN + lane) : 0.f;
            float x1 = lv ? __ldg(nf + (long long)s1 * FIN + lane) : 0.f;
            float x2 = lv ? __ldg(nf + (long long)s2 * FIN + lane) : 0.f;
            float x3 = lv ? __ldg(nf + (long long)s3 * FIN + lane) : 0.f;
            a += (x0 + x1) + (x2 + x3);
        }
        for (; j < rp1; j++) {
            int s = g_csr[j];
            if (lv) a += __ldg(nf + (long long)s * FIN + lane);
        }
        float inv = deg > 0 ? 1.f / (float)deg : 0.f;
        a *= inv;
        float m[FIN];
#pragma unroll
        for (int i = 0; i < FIN; i++) m[i] = __shfl_sync(0xffffffffu, a, i);
        float mk = deg > 0 ? 1.f : 0.f;
        float4 vv = *(const float4*)&sb[lane * 4];
#pragma unroll
        for (int i = 0; i < FIN; i++) {
            float4 w = *(const float4*)&sWt[i * HDIM + lane * 4];
            vv.x = fmaf(m[i], w.x, vv.x); vv.y = fmaf(m[i], w.y, vv.y);
            vv.z = fmaf(m[i], w.z, vv.z); vv.w = fmaf(m[i], w.w, vv.w);
        }
        vv.x *= mk; vv.y *= mk; vv.z *= mk; vv.w *= mk;
        float s  = vv.x + vv.y + vv.z + vv.w;
        float s2 = vv.x * vv.x + vv.y * vv.y + vv.z * vv.z + vv.w * vv.w;
#pragma unroll
        for (int o = 16; o; o >>= 1) {
            s  += __shfl_xor_sync(0xffffffffu, s,  o);
            s2 += __shfl_xor_sync(0xffffffffu, s2, o);
        }
        float mu  = s * (1.f / HDIM);
        float var = s2 * (1.f / HDIM) - mu * mu;
        float rs  = rsqrtf(var + LNEPS);
        float4 g4  = *(const float4*)&sg[lane * 4];
        float4 be4 = *(const float4*)&sbe[lane * 4];
        float y0 = fmaxf((vv.x - mu) * rs * g4.x + be4.x, 0.f);
        float y1 = fmaxf((vv.y - mu) * rs * g4.y + be4.y, 0.f);
        float y2 = fmaxf((vv.z - mu) * rs * g4.z + be4.z, 0.f);
        float y3 = fmaxf((vv.w - mu) * rs * g4.w + be4.w, 0.f);
        __half2 hA = __float22half2_rn(make_float2(y0, y1));
        __half2 hB = __float22half2_rn(make_float2(y2, y3));
        uint2 u; u.x = *(unsigned*)&hA; u.y = *(unsigned*)&hB;
        g_h0h[(size_t)node * 32 + lane] = u;
    }
}

// ---------------- conv1+gemm2 tile kernel: gather(64 nodes) -> HMMA GEMM1 -> LN+ReLU -> HMMA GEMM2 ----------------
#define PITH 136
#define CG_SMEM 104448
#define CG_THREADS 512

__global__ void __launch_bounds__(CG_THREADS) conv1gemm2_mma(
    const float* __restrict__ W1, const float* __restrict__ b1,
    const float* __restrict__ g1, const float* __restrict__ be1,
    const float* __restrict__ W2, const float* __restrict__ b2, int N)
{
    extern __shared__ char smem[];
    __half* W1h = (__half*)(smem);
    __half* W2h = (__half*)(smem + 34816);
    __half* hA  = (__half*)(smem + 52224);
    float*  hC  = (float*)(smem + 69632);
    float*  sb1 = (float*)(smem + 102400);
    float*  sg1 = (float*)(smem + 102912);
    float*  sbe1= (float*)(smem + 103424);
    float*  sb2 = (float*)(smem + 103936);
    float*  smk = (float*)(smem + 104192);
    unsigned sA_base  = (unsigned)__cvta_generic_to_shared(hA);
    unsigned sW1_base = (unsigned)__cvta_generic_to_shared(W1h);
    unsigned sW2_base = (unsigned)__cvta_generic_to_shared(W2h);

    int tid = threadIdx.x;
    for (int i = tid; i < HDIM * HDIM; i += CG_THREADS) {
        int j = i >> 7, k = i & 127;
        W1h[j * PITH + k] = __float2half(W1[i]);
    }
    for (int i = tid; i < DOUT * HDIM; i += CG_THREADS) {
        int j = i >> 7, k = i & 127;
        W2h[j * PITH + k] = __float2half(W2[i]);
    }
    for (int i = tid; i < HDIM; i += CG_THREADS) { sb1[i] = b1[i]; sg1[i] = g1[i]; sbe1[i] = be1[i]; }
    for (int i = tid; i < DOUT; i += CG_THREADS) sb2[i] = b2[i];
    __syncthreads();

    int warp = tid >> 5, lane = tid & 31;
    int nTiles = (N + 63) >> 6;
    for (int tile = blockIdx.x; tile < nTiles; tile += gridDim.x) {
        int tbase = tile << 6;

        // ---- Phase A: gather 4 nodes per warp into hA (fp16), record mask ----
#pragma unroll
        for (int q = 0; q < 4; q++) {
            int nl = warp * 4 + q;
            int node = tbase + nl;
            float4 acc = make_float4(0.f, 0.f, 0.f, 0.f);
            float mk = 0.f;
            if (node < N) {
                int rp0 = g_rowptr[node], rp1 = g_rowptr[node + 1];
                int j = rp0;
                for (; j + 3 < rp1; j += 4) {
                    uint2 r0 = g_h0h[(size_t)g_csr[j]     * 32 + lane];
                    uint2 r1 = g_h0h[(size_t)g_csr[j + 1] * 32 + lane];
                    uint2 r2 = g_h0h[(size_t)g_csr[j + 2] * 32 + lane];
                    uint2 r3 = g_h0h[(size_t)g_csr[j + 3] * 32 + lane];
                    add_h4(acc, r0); add_h4(acc, r1); add_h4(acc, r2); add_h4(acc, r3);
                }
                for (; j < rp1; j++) {
                    uint2 r = g_h0h[(size_t)g_csr[j] * 32 + lane];
                    add_h4(acc, r);
                }
                int deg = rp1 - rp0;
                float inv = deg > 0 ? 1.f / (float)deg : 0.f;
                mk = deg > 0 ? 1.f : 0.f;
                acc.x *= inv; acc.y *= inv; acc.z *= inv; acc.w *= inv;
            }
            __half2 hx = __float22half2_rn(make_float2(acc.x, acc.y));
            __half2 hy = __float22half2_rn(make_float2(acc.z, acc.w));
            uint2 u; u.x = *(unsigned*)&hx; u.y = *(unsigned*)&hy;
            *(uint2*)((char*)hA + nl * (PITH * 2) + lane * 8) = u;
            if (lane == 0) smk[nl] = mk;
        }
        __syncthreads();

        // ---- Phase B: GEMM1  hC[64][128] = hA[64][128] @ W1^T ----
        {
            int mt = warp & 3, nt = warp >> 2;
            int m0 = mt * 16, n0 = nt * 32;
            float C[4][4];
#pragma unroll
            for (int s = 0; s < 4; s++) { C[s][0] = C[s][1] = C[s][2] = C[s][3] = 0.f; }
            unsigned arow = (unsigned)(m0 + (lane & 15));
            unsigned akof = (unsigned)((lane >> 4) << 3);
#pragma unroll
            for (int k0 = 0; k0 < HDIM; k0 += 16) {
                unsigned a0, a1, a2, a3;
                ldm_x4(a0, a1, a2, a3, sA_base + (arow * PITH + k0 + akof) * 2);
#pragma unroll
                for (int s = 0; s < 4; s++) {
                    unsigned brow = (unsigned)(n0 + s * 8 + (lane & 7));
                    unsigned bkof = (unsigned)(k0 + ((lane >> 3) & 1) * 8);
                    unsigned b0, b1;
                    ldm_x2(b0, b1, sW1_base + (brow * PITH + bkof) * 2);
                    mma16816(C[s], a0, a1, a2, a3, b0, b1);
                }
            }
            int g = lane >> 2, cc = (lane & 3) * 2;
#pragma unroll
            for (int s = 0; s < 4; s++) {
                int col = n0 + s * 8 + cc;
                *(float2*)&hC[(m0 + g) * HDIM + col]     = make_float2(C[s][0], C[s][1]);
                *(float2*)&hC[(m0 + g + 8) * HDIM + col] = make_float2(C[s][2], C[s][3]);
            }
        }
        __syncthreads();

        // ---- Phase C: LN + ReLU per row, write fp16 back to hA ----
#pragma unroll
        for (int r = 0; r < 4; r++) {
            int row = warp * 4 + r;
            float4 v  = *(const float4*)&hC[row * HDIM + lane * 4];
            float4 b4 = *(const float4*)&sb1[lane * 4];
            float mk  = smk[row];
            float v0 = (v.x + b4.x) * mk, v1 = (v.y + b4.y) * mk;
            float v2 = (v.z + b4.z) * mk, v3 = (v.w + b4.w) * mk;
            float s  = v0 + v1 + v2 + v3;
            float s2 = v0 * v0 + v1 * v1 + v2 * v2 + v3 * v3;
#pragma unroll
            for (int o = 16; o; o >>= 1) {
                s  += __shfl_xor_sync(0xffffffffu, s,  o);
                s2 += __shfl_xor_sync(0xffffffffu, s2, o);
            }
            float mu  = s * (1.f / HDIM);
            float var = s2 * (1.f / HDIM) - mu * mu;
            float rs  = rsqrtf(var + LNEPS);
            float4 g4  = *(const float4*)&sg1[lane * 4];
            float4 be4 = *(const float4*)&sbe1[lane * 4];
            float y0 = fmaxf((v0 - mu) * rs * g4.x + be4.x, 0.f);
            float y1 = fmaxf((v1 - mu) * rs * g4.y + be4.y, 0.f);
            float y2 = fmaxf((v2 - mu) * rs * g4.z + be4.z, 0.f);
            float y3 = fmaxf((v3 - mu) * rs * g4.w + be4.w, 0.f);
            __half2 h01 = __float22half2_rn(make_float2(y0, y1));
            __half2 h23 = __float22half2_rn(make_float2(y2, y3));
            uint2 u; u.x = *(unsigned*)&h01; u.y = *(unsigned*)&h23;
            *(uint2*)((char*)hA + row * (PITH * 2) + lane * 8) = u;
        }
        __syncthreads();

        // ---- Phase D: GEMM2  xt2[64][64] = h1[64][128] @ W2^T + b2, store fp16 to global ----
        {
            int mt = warp & 3, nt = warp >> 2;
            int m0 = mt * 16, n0 = nt * 16;
            float C[2][4];
#pragma unroll
            for (int s = 0; s < 2; s++) { C[s][0] = C[s][1] = C[s][2] = C[s][3] = 0.f; }
            unsigned arow = (unsigned)(m0 + (lane & 15));
            unsigned akof = (unsigned)((lane >> 4) << 3);
#pragma unroll
            for (int k0 = 0; k0 < HDIM; k0 += 16) {
                unsigned a0, a1, a2, a3;
                ldm_x4(a0, a1, a2, a3, sA_base + (arow * PITH + k0 + akof) * 2);
#pragma unroll
                for (int s = 0; s < 2; s++) {
                    unsigned brow = (unsigned)(n0 + s * 8 + (lane & 7));
                    unsigned bkof = (unsigned)(k0 + ((lane >> 3) & 1) * 8);
                    unsigned b0, b1;
                    ldm_x2(b0, b1, sW2_base + (brow * PITH + bkof) * 2);
                    mma16816(C[s], a0, a1, a2, a3, b0, b1);
                }
            }
            int g = lane >> 2, cc = (lane & 3) * 2;
#pragma unroll
            for (int s = 0; s < 2; s++) {
                int col = n0 + s * 8 + cc;
                float bx = sb2[col], by = sb2[col + 1];
                int r0 = tbase + m0 + g, r1 = r0 + 8;
                if (r0 < N) {
                    __half2 h = __float22half2_rn(make_float2(C[s][0] + bx, C[s][1] + by));
                    g_xt2h[(size_t)r0 * 32 + (col >> 1)] = *(unsigned*)&h;
                }
                if (r1 < N) {
                    __half2 h = __float22half2_rn(make_float2(C[s][2] + bx, C[s][3] + by));
                    g_xt2h[(size_t)r1 * 32 + (col >> 1)] = *(unsigned*)&h;
                }
            }
        }
        __syncthreads();   // hA reused by next tile's gather
    }
}

// ---------------- final: gather xt2(fp16) -> LN -> out, warp per node ----------------
__global__ void final_fused(const float* __restrict__ g2, const float* __restrict__ be2,
                            float* __restrict__ out, int N) {
    int lane   = threadIdx.x & 31;
    int gwarp  = (blockIdx.x * blockDim.x + threadIdx.x) >> 5;
    int nwarps = (gridDim.x * blockDim.x) >> 5;
    float gA = g2[lane * 2], gB = g2[lane * 2 + 1];
    float bA = be2[lane * 2], bB = be2[lane * 2 + 1];
    for (int node = gwarp; node < N; node += nwarps) {
        int rp0 = g_rowptr[node], rp1 = g_rowptr[node + 1];
        int deg = rp1 - rp0;
        float2 acc = make_float2(0.f, 0.f);
        int j = rp0;
        for (; j + 3 < rp1; j += 4) {
            unsigned r0 = g_xt2h[(size_t)g_csr[j]     * 32 + lane];
            unsigned r1 = g_xt2h[(size_t)g_csr[j + 1] * 32 + lane];
            unsigned r2 = g_xt2h[(size_t)g_csr[j + 2] * 32 + lane];
            unsigned r3 = g_xt2h[(size_t)g_csr[j + 3] * 32 + lane];
            float2 v0 = __half22float2(*(__half2*)&r0);
            float2 v1 = __half22float2(*(__half2*)&r1);
            float2 v2 = __half22float2(*(__half2*)&r2);
            float2 v3 = __half22float2(*(__half2*)&r3);
            acc.x += (v0.x + v1.x) + (v2.x + v3.x);
            acc.y += (v0.y + v1.y) + (v2.y + v3.y);
        }
        for (; j < rp1; j++) {
            unsigned r = g_xt2h[(size_t)g_csr[j] * 32 + lane];
            float2 v = __half22float2(*(__half2*)&r);
            acc.x += v.x; acc.y += v.y;
        }
        float inv = deg > 0 ? 1.f / (float)deg : 1.f;
        acc.x *= inv; acc.y *= inv;
        float s  = acc.x + acc.y;
        float s2 = acc.x * acc.x + acc.y * acc.y;
#pragma unroll
        for (int o = 16; o; o >>= 1) {
            s  += __shfl_xor_sync(0xffffffffu, s,  o);
            s2 += __shfl_xor_sync(0xffffffffu, s2, o);
        }
        float mu  = s * (1.f / DOUT);
        float var = s2 * (1.f / DOUT) - mu * mu;
        float rs  = rsqrtf(var + LNEPS);
        float2 o2;
        o2.x = (acc.x - mu) * rs * gA + bA;
        o2.y = (acc.y - mu) * rs * gB + bB;
        *(float2*)(out + (long long)node * DOUT + lane * 2) = o2;
    }
}

// ---------------- launch ----------------
extern "C" void kernel_launch(void* const* d_in, const int* in_sizes, int n_in,
                              void* d_out, int out_size) {
    const float* nf  = (const float*)d_in[0];
    const int*   ei  = (const int*)d_in[1];
    const float* W0  = (const float*)d_in[2];
    const float* b0  = (const float*)d_in[3];
    const float* W1  = (const float*)d_in[4];
    const float* b1  = (const float*)d_in[5];
    const float* W2  = (const float*)d_in[6];
    const float* b2  = (const float*)d_in[7];
    const float* g0  = (const float*)d_in[8];
    const float* be0 = (const float*)d_in[9];
    const float* g1  = (const float*)d_in[10];
    const float* be1 = (const float*)d_in[11];
    const float* g2  = (const float*)d_in[12];
    const float* be2 = (const float*)d_in[13];
    int N = in_sizes[0] / FIN;
    int E = in_sizes[1] / 2;
    int NB = (N + SCAN_BS - 1) / SCAN_BS;

    cudaFuncSetAttribute(conv1gemm2_mma, cudaFuncAttributeMaxDynamicSharedMemorySize, CG_SMEM);

    // CSR build (incoming edges grouped by target)
    zero_cnt<<<(N + 255) / 256, 256>>>(N);
    count_edges<<<(E + 255) / 256, 256>>>(ei, E);
    scan_partial<<<NB, SCAN_BS>>>(N);
    scan_bsums<<<1, MAXNB>>>(NB);
    scan_final<<<NB, SCAN_BS>>>(N, E);
    fill_csr<<<(E + 255) / 256, 256>>>(ei, E);

    // layers
    conv0_fused<<<1480, 256>>>(nf, W0, b0, g0, be0, N);
    conv1gemm2_mma<<<304, CG_THREADS, CG_SMEM>>>(W1, b1, g1, be1, W2, b2, N);
    final_fused<<<1480, 256>>>(g2, be2, (float*)d_out, N);
}

// round 12
// speedup vs baseline: 4.2649x; 1.0828x over previous
#include <cuda_runtime.h>
#include <cuda_fp16.h>

#define NMAX 100000
#define EMAX 1600000
#define FIN  11
#define HDIM 128
#define DOUT 64
#define LNEPS 1e-5f
#define SCAN_BS 1024
#define MAXNB 128

// ---------------- scratch (static device globals; no runtime allocation) ----------------
__device__ int   g_rowptr[NMAX + 1];
__device__ int   g_cnt   [NMAX];
__device__ int   g_csr   [EMAX];
__device__ int   g_bsum  [MAXNB];
__device__ int   g_boff  [MAXNB];
__device__ uint2    g_h0h [NMAX * 32];   // h0 in fp16: 128 halves/row = 32 uint2
__device__ unsigned g_xt2h[NMAX * 32];   // xt2 in fp16: 64 halves/row = 32 half2

__device__ __forceinline__ void add_h4(float4& a, uint2 r) {
    float2 lo = __half22float2(*(__half2*)&r.x);
    float2 hi = __half22float2(*(__half2*)&r.y);
    a.x += lo.x; a.y += lo.y; a.z += hi.x; a.w += hi.y;
}

// ---------------- mma helpers ----------------
__device__ __forceinline__ void ldm_x4(unsigned& a0, unsigned& a1, unsigned& a2, unsigned& a3, unsigned addr) {
    asm volatile("ldmatrix.sync.aligned.m8n8.x4.shared.b16 {%0,%1,%2,%3}, [%4];"
                 : "=r"(a0), "=r"(a1), "=r"(a2), "=r"(a3) : "r"(addr));
}
// B stored [n][k] row-major is already K-major ("col-major B") -> NON-trans ldmatrix
__device__ __forceinline__ void ldm_x2(unsigned& b0, unsigned& b1, unsigned addr) {
    asm volatile("ldmatrix.sync.aligned.m8n8.x2.shared.b16 {%0,%1}, [%2];"
                 : "=r"(b0), "=r"(b1) : "r"(addr));
}
__device__ __forceinline__ void mma16816(float* c, unsigned a0, unsigned a1, unsigned a2, unsigned a3,
                                         unsigned b0, unsigned b1) {
    asm volatile("mma.sync.aligned.m16n8k16.row.col.f32.f16.f16.f32 "
                 "{%0,%1,%2,%3}, {%4,%5,%6,%7}, {%8,%9}, {%0,%1,%2,%3};"
                 : "+f"(c[0]), "+f"(c[1]), "+f"(c[2]), "+f"(c[3])
                 : "r"(a0), "r"(a1), "r"(a2), "r"(a3), "r"(b0), "r"(b1));
}

// ---------------- CSR build ----------------
__global__ void zero_cnt(int N) {
    int i = blockIdx.x * blockDim.x + threadIdx.x;
    if (i < N) g_cnt[i] = 0;
}
__global__ void count_edges(const int* __restrict__ ei, int E) {
    int e = blockIdx.x * blockDim.x + threadIdx.x;
    if (e < E) atomicAdd(&g_cnt[ei[E + e]], 1);
}
__global__ void scan_partial(int N) {
    __shared__ int sh[SCAN_BS];
    int t = threadIdx.x;
    int i = blockIdx.x * SCAN_BS + t;
    sh[t] = (i < N) ? g_cnt[i] : 0;
    __syncthreads();
    for (int off = SCAN_BS / 2; off; off >>= 1) {
        if (t < off) sh[t] += sh[t + off];
        __syncthreads();
    }
    if (t == 0) g_bsum[blockIdx.x] = sh[0];
}
__global__ void scan_bsums(int NB) {
    __shared__ int sh[MAXNB];
    int t = threadIdx.x;
    int v = (t < NB) ? g_bsum[t] : 0;
    sh[t] = v;
    __syncthreads();
    for (int off = 1; off < MAXNB; off <<= 1) {
        int x = (t >= off) ? sh[t - off] : 0;
        __syncthreads();
        sh[t] += x;
        __syncthreads();
    }
    if (t < NB) g_boff[t] = sh[t] - v;
}
__global__ void scan_final(int N, int E) {
    __shared__ int sh[SCAN_BS];
    int t = threadIdx.x;
    int i = blockIdx.x * SCAN_BS + t;
    int v = (i < N) ? g_cnt[i] : 0;
    sh[t] = v;
    __syncthreads();
    for (int off = 1; off < SCAN_BS; off <<= 1) {
        int x = (t >= off) ? sh[t - off] : 0;
        __syncthreads();
        sh[t] += x;
        __syncthreads();
    }
    if (i < N) {
        g_rowptr[i] = g_boff[blockIdx.x] + sh[t] - v;
        g_cnt[i] = 0;
    }
    if (i == 0) g_rowptr[N] = E;
}
__global__ void fill_csr(const int* __restrict__ ei, int E) {
    int e = blockIdx.x * blockDim.x + threadIdx.x;
    if (e >= E) return;
    int s = ei[e], t = ei[E + e];
    int pos = atomicAdd(&g_cnt[t], 1);
    g_csr[g_rowptr[t] + pos] = s;
}

// ---------------- conv0: gather@11 (half-warp per edge) + GEMM + LN + ReLU -> h0 (fp16) ----------------
__global__ void conv0_fused(const float* __restrict__ nf,
                            const float* __restrict__ W0, const float* __restrict__ b0,
                            const float* __restrict__ g0, const float* __restrict__ be0, int N) {
    __shared__ __align__(16) float sWt[FIN * HDIM];
    __shared__ __align__(16) float sb[HDIM], sg[HDIM], sbe[HDIM];
    for (int idx = threadIdx.x; idx < FIN * HDIM; idx += blockDim.x) {
        int i = idx >> 7, j = idx & 127;
        sWt[i * HDIM + j] = W0[j * FIN + i];
    }
    for (int i = threadIdx.x; i < HDIM; i += blockDim.x) { sb[i] = b0[i]; sg[i] = g0[i]; sbe[i] = be0[i]; }
    __syncthreads();
    int lane   = threadIdx.x & 31;
    int gwarp  = (blockIdx.x * blockDim.x + threadIdx.x) >> 5;
    int nwarps = (gridDim.x * blockDim.x) >> 5;
    int half = lane >> 4;      // 0: even CSR slots, 1: odd
    int f    = lane & 15;      // feature index
    bool lv  = f < FIN;
    for (int node = gwarp; node < N; node += nwarps) {
        int rp0 = g_rowptr[node], rp1 = g_rowptr[node + 1];
        int deg = rp1 - rp0;
        float a = 0.f;
        int j = rp0;
        // 8 edges per iteration: each half-warp covers 4 (even/odd interleave), MLP=4 per lane
        for (; j + 7 < rp1; j += 8) {
            int s0 = g_csr[j + half],     s1 = g_csr[j + 2 + half];
            int s2 = g_csr[j + 4 + half], s3 = g_csr[j + 6 + half];
            float x0 = lv ? __ldg(nf + (long long)s0 * FIN + f) : 0.f;
            float x1 = lv ? __ldg(nf + (long long)s1 * FIN + f) : 0.f;
            float x2 = lv ? __ldg(nf + (long long)s2 * FIN + f) : 0.f;
            float x3 = lv ? __ldg(nf + (long long)s3 * FIN + f) : 0.f;
            a += (x0 + x1) + (x2 + x3);
        }
        for (; j + 1 < rp1; j += 2) {
            int s = g_csr[j + half];
            if (lv) a += __ldg(nf + (long long)s * FIN + f);
        }
        if (j < rp1 && half == 0) {
            int s = g_csr[j];
            if (lv) a += __ldg(nf + (long long)s * FIN + f);
        }
        float inv = deg > 0 ? 1.f / (float)deg : 0.f;
        float m[FIN];
#pragma unroll
        for (int i = 0; i < FIN; i++)
            m[i] = (__shfl_sync(0xffffffffu, a, i) + __shfl_sync(0xffffffffu, a, i + 16)) * inv;
        float mk = deg > 0 ? 1.f : 0.f;
        float4 vv = *(const float4*)&sb[lane * 4];
#pragma unroll
        for (int i = 0; i < FIN; i++) {
            float4 w = *(const float4*)&sWt[i * HDIM + lane * 4];
            vv.x = fmaf(m[i], w.x, vv.x); vv.y = fmaf(m[i], w.y, vv.y);
            vv.z = fmaf(m[i], w.z, vv.z); vv.w = fmaf(m[i], w.w, vv.w);
        }
        vv.x *= mk; vv.y *= mk; vv.z *= mk; vv.w *= mk;
        float s  = vv.x + vv.y + vv.z + vv.w;
        float s2 = vv.x * vv.x + vv.y * vv.y + vv.z * vv.z + vv.w * vv.w;
#pragma unroll
        for (int o = 16; o; o >>= 1) {
            s  += __shfl_xor_sync(0xffffffffu, s,  o);
            s2 += __shfl_xor_sync(0xffffffffu, s2, o);
        }
        float mu  = s * (1.f / HDIM);
        float var = s2 * (1.f / HDIM) - mu * mu;
        float rs  = rsqrtf(var + LNEPS);
        float4 g4  = *(const float4*)&sg[lane * 4];
        float4 be4 = *(const float4*)&sbe[lane * 4];
        float y0 = fmaxf((vv.x - mu) * rs * g4.x + be4.x, 0.f);
        float y1 = fmaxf((vv.y - mu) * rs * g4.y + be4.y, 0.f);
        float y2 = fmaxf((vv.z - mu) * rs * g4.z + be4.z, 0.f);
        float y3 = fmaxf((vv.w - mu) * rs * g4.w + be4.w, 0.f);
        __half2 hA = __float22half2_rn(make_float2(y0, y1));
        __half2 hB = __float22half2_rn(make_float2(y2, y3));
        uint2 u; u.x = *(unsigned*)&hA; u.y = *(unsigned*)&hB;
        g_h0h[(size_t)node * 32 + lane] = u;
    }
}

// ---------------- conv1+gemm2 tile kernel: gather(64 nodes) -> HMMA GEMM1 -> LN+ReLU -> HMMA GEMM2 ----------------
#define PITH 136
#define CG_SMEM 104448
#define CG_THREADS 512

__global__ void __launch_bounds__(CG_THREADS) conv1gemm2_mma(
    const float* __restrict__ W1, const float* __restrict__ b1,
    const float* __restrict__ g1, const float* __restrict__ be1,
    const float* __restrict__ W2, const float* __restrict__ b2, int N)
{
    extern __shared__ char smem[];
    __half* W1h = (__half*)(smem);
    __half* W2h = (__half*)(smem + 34816);
    __half* hA  = (__half*)(smem + 52224);
    float*  hC  = (float*)(smem + 69632);
    float*  sb1 = (float*)(smem + 102400);
    float*  sg1 = (float*)(smem + 102912);
    float*  sbe1= (float*)(smem + 103424);
    float*  sb2 = (float*)(smem + 103936);
    float*  smk = (float*)(smem + 104192);
    unsigned sA_base  = (unsigned)__cvta_generic_to_shared(hA);
    unsigned sW1_base = (unsigned)__cvta_generic_to_shared(W1h);
    unsigned sW2_base = (unsigned)__cvta_generic_to_shared(W2h);

    int tid = threadIdx.x;
    for (int i = tid; i < HDIM * HDIM; i += CG_THREADS) {
        int j = i >> 7, k = i & 127;
        W1h[j * PITH + k] = __float2half(W1[i]);
    }
    for (int i = tid; i < DOUT * HDIM; i += CG_THREADS) {
        int j = i >> 7, k = i & 127;
        W2h[j * PITH + k] = __float2half(W2[i]);
    }
    for (int i = tid; i < HDIM; i += CG_THREADS) { sb1[i] = b1[i]; sg1[i] = g1[i]; sbe1[i] = be1[i]; }
    for (int i = tid; i < DOUT; i += CG_THREADS) sb2[i] = b2[i];
    __syncthreads();

    int warp = tid >> 5, lane = tid & 31;
    int nTiles = (N + 63) >> 6;
    for (int tile = blockIdx.x; tile < nTiles; tile += gridDim.x) {
        int tbase = tile << 6;

        // ---- Phase A: gather 4 nodes per warp into hA (fp16), MLP=8 ----
#pragma unroll
        for (int q = 0; q < 4; q++) {
            int nl = warp * 4 + q;
            int node = tbase + nl;
            float4 acc = make_float4(0.f, 0.f, 0.f, 0.f);
            float mk = 0.f;
            if (node < N) {
                int rp0 = g_rowptr[node], rp1 = g_rowptr[node + 1];
                int j = rp0;
                for (; j + 7 < rp1; j += 8) {
                    uint2 r0 = g_h0h[(size_t)g_csr[j]     * 32 + lane];
                    uint2 r1 = g_h0h[(size_t)g_csr[j + 1] * 32 + lane];
                    uint2 r2 = g_h0h[(size_t)g_csr[j + 2] * 32 + lane];
                    uint2 r3 = g_h0h[(size_t)g_csr[j + 3] * 32 + lane];
                    uint2 r4 = g_h0h[(size_t)g_csr[j + 4] * 32 + lane];
                    uint2 r5 = g_h0h[(size_t)g_csr[j + 5] * 32 + lane];
                    uint2 r6 = g_h0h[(size_t)g_csr[j + 6] * 32 + lane];
                    uint2 r7 = g_h0h[(size_t)g_csr[j + 7] * 32 + lane];
                    add_h4(acc, r0); add_h4(acc, r1); add_h4(acc, r2); add_h4(acc, r3);
                    add_h4(acc, r4); add_h4(acc, r5); add_h4(acc, r6); add_h4(acc, r7);
                }
                for (; j < rp1; j++) {
                    uint2 r = g_h0h[(size_t)g_csr[j] * 32 + lane];
                    add_h4(acc, r);
                }
                int deg = rp1 - rp0;
                float inv = deg > 0 ? 1.f / (float)deg : 0.f;
                mk = deg > 0 ? 1.f : 0.f;
                acc.x *= inv; acc.y *= inv; acc.z *= inv; acc.w *= inv;
            }
            __half2 hx = __float22half2_rn(make_float2(acc.x, acc.y));
            __half2 hy = __float22half2_rn(make_float2(acc.z, acc.w));
            uint2 u; u.x = *(unsigned*)&hx; u.y = *(unsigned*)&hy;
            *(uint2*)((char*)hA + nl * (PITH * 2) + lane * 8) = u;
            if (lane == 0) smk[nl] = mk;
        }
        __syncthreads();

        // ---- Phase B: GEMM1  hC[64][128] = hA[64][128] @ W1^T ----
        {
            int mt = warp & 3, nt = warp >> 2;
            int m0 = mt * 16, n0 = nt * 32;
            float C[4][4];
#pragma unroll
            for (int s = 0; s < 4; s++) { C[s][0] = C[s][1] = C[s][2] = C[s][3] = 0.f; }
            unsigned arow = (unsigned)(m0 + (lane & 15));
            unsigned akof = (unsigned)((lane >> 4) << 3);
#pragma unroll
            for (int k0 = 0; k0 < HDIM; k0 += 16) {
                unsigned a0, a1, a2, a3;
                ldm_x4(a0, a1, a2, a3, sA_base + (arow * PITH + k0 + akof) * 2);
#pragma unroll
                for (int s = 0; s < 4; s++) {
                    unsigned brow = (unsigned)(n0 + s * 8 + (lane & 7));
                    unsigned bkof = (unsigned)(k0 + ((lane >> 3) & 1) * 8);
                    unsigned b0, b1;
                    ldm_x2(b0, b1, sW1_base + (brow * PITH + bkof) * 2);
                    mma16816(C[s], a0, a1, a2, a3, b0, b1);
                }
            }
            int g = lane >> 2, cc = (lane & 3) * 2;
#pragma unroll
            for (int s = 0; s < 4; s++) {
                int col = n0 + s * 8 + cc;
                *(float2*)&hC[(m0 + g) * HDIM + col]     = make_float2(C[s][0], C[s][1]);
                *(float2*)&hC[(m0 + g + 8) * HDIM + col] = make_float2(C[s][2], C[s][3]);
            }
        }
        __syncthreads();

        // ---- Phase C: LN + ReLU per row, write fp16 back to hA ----
#pragma unroll
        for (int r = 0; r < 4; r++) {
            int row = warp * 4 + r;
            float4 v  = *(const float4*)&hC[row * HDIM + lane * 4];
            float4 b4 = *(const float4*)&sb1[lane * 4];
            float mk  = smk[row];
            float v0 = (v.x + b4.x) * mk, v1 = (v.y + b4.y) * mk;
            float v2 = (v.z + b4.z) * mk, v3 = (v.w + b4.w) * mk;
            float s  = v0 + v1 + v2 + v3;
            float s2 = v0 * v0 + v1 * v1 + v2 * v2 + v3 * v3;
#pragma unroll
            for (int o = 16; o; o >>= 1) {
                s  += __shfl_xor_sync(0xffffffffu, s,  o);
                s2 += __shfl_xor_sync(0xffffffffu, s2, o);
            }
            float mu  = s * (1.f / HDIM);
            float var = s2 * (1.f / HDIM) - mu * mu;
            float rs  = rsqrtf(var + LNEPS);
            float4 g4  = *(const float4*)&sg1[lane * 4];
            float4 be4 = *(const float4*)&sbe1[lane * 4];
            float y0 = fmaxf((v0 - mu) * rs * g4.x + be4.x, 0.f);
            float y1 = fmaxf((v1 - mu) * rs * g4.y + be4.y, 0.f);
            float y2 = fmaxf((v2 - mu) * rs * g4.z + be4.z, 0.f);
            float y3 = fmaxf((v3 - mu) * rs * g4.w + be4.w, 0.f);
            __half2 h01 = __float22half2_rn(make_float2(y0, y1));
            __half2 h23 = __float22half2_rn(make_float2(y2, y3));
            uint2 u; u.x = *(unsigned*)&h01; u.y = *(unsigned*)&h23;
            *(uint2*)((char*)hA + row * (PITH * 2) + lane * 8) = u;
        }
        __syncthreads();

        // ---- Phase D: GEMM2  xt2[64][64] = h1[64][128] @ W2^T + b2, store fp16 to global ----
        {
            int mt = warp & 3, nt = warp >> 2;
            int m0 = mt * 16, n0 = nt * 16;
            float C[2][4];
#pragma unroll
            for (int s = 0; s < 2; s++) { C[s][0] = C[s][1] = C[s][2] = C[s][3] = 0.f; }
            unsigned arow = (unsigned)(m0 + (lane & 15));
            unsigned akof = (unsigned)((lane >> 4) << 3);
#pragma unroll
            for (int k0 = 0; k0 < HDIM; k0 += 16) {
                unsigned a0, a1, a2, a3;
                ldm_x4(a0, a1, a2, a3, sA_base + (arow * PITH + k0 + akof) * 2);
#pragma unroll
                for (int s = 0; s < 2; s++) {
                    unsigned brow = (unsigned)(n0 + s * 8 + (lane & 7));
                    unsigned bkof = (unsigned)(k0 + ((lane >> 3) & 1) * 8);
                    unsigned b0, b1;
                    ldm_x2(b0, b1, sW2_base + (brow * PITH + bkof) * 2);
                    mma16816(C[s], a0, a1, a2, a3, b0, b1);
                }
            }
            int g = lane >> 2, cc = (lane & 3) * 2;
#pragma unroll
            for (int s = 0; s < 2; s++) {
                int col = n0 + s * 8 + cc;
                float bx = sb2[col], by = sb2[col + 1];
                int r0 = tbase + m0 + g, r1 = r0 + 8;
                if (r0 < N) {
                    __half2 h = __float22half2_rn(make_float2(C[s][0] + bx, C[s][1] + by));
                    g_xt2h[(size_t)r0 * 32 + (col >> 1)] = *(unsigned*)&h;
                }
                if (r1 < N) {
                    __half2 h = __float22half2_rn(make_float2(C[s][2] + bx, C[s][3] + by));
                    g_xt2h[(size_t)r1 * 32 + (col >> 1)] = *(unsigned*)&h;
                }
            }
        }
        __syncthreads();   // hA reused by next tile's gather
    }
}

// ---------------- final: gather xt2(fp16) -> LN -> out, warp per node, MLP=8 ----------------
__global__ void final_fused(const float* __restrict__ g2, const float* __restrict__ be2,
                            float* __restrict__ out, int N) {
    int lane   = threadIdx.x & 31;
    int gwarp  = (blockIdx.x * blockDim.x + threadIdx.x) >> 5;
    int nwarps = (gridDim.x * blockDim.x) >> 5;
    float gA = g2[lane * 2], gB = g2[lane * 2 + 1];
    float bA = be2[lane * 2], bB = be2[lane * 2 + 1];
    for (int node = gwarp; node < N; node += nwarps) {
        int rp0 = g_rowptr[node], rp1 = g_rowptr[node + 1];
        int deg = rp1 - rp0;
        float2 acc = make_float2(0.f, 0.f);
        int j = rp0;
        for (; j + 7 < rp1; j += 8) {
            unsigned r0 = g_xt2h[(size_t)g_csr[j]     * 32 + lane];
            unsigned r1 = g_xt2h[(size_t)g_csr[j + 1] * 32 + lane];
            unsigned r2 = g_xt2h[(size_t)g_csr[j + 2] * 32 + lane];
            unsigned r3 = g_xt2h[(size_t)g_csr[j + 3] * 32 + lane];
            unsigned r4 = g_xt2h[(size_t)g_csr[j + 4] * 32 + lane];
            unsigned r5 = g_xt2h[(size_t)g_csr[j + 5] * 32 + lane];
            unsigned r6 = g_xt2h[(size_t)g_csr[j + 6] * 32 + lane];
            unsigned r7 = g_xt2h[(size_t)g_csr[j + 7] * 32 + lane];
            float2 v0 = __half22float2(*(__half2*)&r0);
            float2 v1 = __half22float2(*(__half2*)&r1);
            float2 v2 = __half22float2(*(__half2*)&r2);
            float2 v3 = __half22float2(*(__half2*)&r3);
            float2 v4 = __half22float2(*(__half2*)&r4);
            float2 v5 = __half22float2(*(__half2*)&r5);
            float2 v6 = __half22float2(*(__half2*)&r6);
            float2 v7 = __half22float2(*(__half2*)&r7);
            acc.x += ((v0.x + v1.x) + (v2.x + v3.x)) + ((v4.x + v5.x) + (v6.x + v7.x));
            acc.y += ((v0.y + v1.y) + (v2.y + v3.y)) + ((v4.y + v5.y) + (v6.y + v7.y));
        }
        for (; j < rp1; j++) {
            unsigned r = g_xt2h[(size_t)g_csr[j] * 32 + lane];
            float2 v = __half22float2(*(__half2*)&r);
            acc.x += v.x; acc.y += v.y;
        }
        float inv = deg > 0 ? 1.f / (float)deg : 1.f;
        acc.x *= inv; acc.y *= inv;
        float s  = acc.x + acc.y;
        float s2 = acc.x * acc.x + acc.y * acc.y;
#pragma unroll
        for (int o = 16; o; o >>= 1) {
            s  += __shfl_xor_sync(0xffffffffu, s,  o);
            s2 += __shfl_xor_sync(0xffffffffu, s2, o);
        }
        float mu  = s * (1.f / DOUT);
        float var = s2 * (1.f / DOUT) - mu * mu;
        float rs  = rsqrtf(var + LNEPS);
        float2 o2;
        o2.x = (acc.x - mu) * rs * gA + bA;
        o2.y = (acc.y - mu) * rs * gB + bB;
        *(float2*)(out + (long long)node * DOUT + lane * 2) = o2;
    }
}

// ---------------- launch ----------------
extern "C" void kernel_launch(void* const* d_in, const int* in_sizes, int n_in,
                              void* d_out, int out_size) {
    const float* nf  = (const float*)d_in[0];
    const int*   ei  = (const int*)d_in[1];
    const float* W0  = (const float*)d_in[2];
    const float* b0  = (const float*)d_in[3];
    const float* W1  = (const float*)d_in[4];
    const float* b1  = (const float*)d_in[5];
    const float* W2  = (const float*)d_in[6];
    const float* b2  = (const float*)d_in[7];
    const float* g0  = (const float*)d_in[8];
    const float* be0 = (const float*)d_in[9];
    const float* g1  = (const float*)d_in[10];
    const float* be1 = (const float*)d_in[11];
    const float* g2  = (const float*)d_in[12];
    const float* be2 = (const float*)d_in[13];
    int N = in_sizes[0] / FIN;
    int E = in_sizes[1] / 2;
    int NB = (N + SCAN_BS - 1) / SCAN_BS;

    cudaFuncSetAttribute(conv1gemm2_mma, cudaFuncAttributeMaxDynamicSharedMemorySize, CG_SMEM);

    // CSR build (incoming edges grouped by target)
    zero_cnt<<<(N + 255) / 256, 256>>>(N);
    count_edges<<<(E + 255) / 256, 256>>>(ei, E);
    scan_partial<<<NB, SCAN_BS>>>(N);
    scan_bsums<<<1, MAXNB>>>(NB);
    scan_final<<<NB, SCAN_BS>>>(N, E);
    fill_csr<<<(E + 255) / 256, 256>>>(ei, E);

    // layers
    conv0_fused<<<1480, 256>>>(nf, W0, b0, g0, be0, N);
    conv1gemm2_mma<<<304, CG_THREADS, CG_SMEM>>>(W1, b1, g1, be1, W2, b2, N);
    final_fused<<<1480, 256>>>(g2, be2, (float*)d_out, N);
}

// round 14
// speedup vs baseline: 4.2932x; 1.0066x over previous
#include <cuda_runtime.h>
#include <cuda_fp16.h>

#define NMAX 100000
#define EMAX 1600000
#define FIN  11
#define HDIM 128
#define DOUT 64
#define LNEPS 1e-5f
#define SCAN_BS 1024
#define MAXNB 128

// ---------------- scratch (static device globals; no runtime allocation) ----------------
__device__ int   g_rowptr[NMAX + 1];
__device__ int   g_cnt   [NMAX];      // counts; fill_csr decrements back to 0 each launch
__device__ int   g_csr   [EMAX];
__device__ int   g_bsum  [MAXNB];
__device__ int   g_tile;              // dynamic tile cursor for conv1gemm2 (reset by count_edges)
__device__ uint2    g_h0h [NMAX * 32];   // h0 in fp16: 128 halves/row = 32 uint2
__device__ unsigned g_xt2h[NMAX * 32];   // xt2 in fp16: 64 halves/row = 32 half2

__device__ __forceinline__ void add_h4(float4& a, uint2 r) {
    float2 lo = __half22float2(*(__half2*)&r.x);
    float2 hi = __half22float2(*(__half2*)&r.y);
    a.x += lo.x; a.y += lo.y; a.z += hi.x; a.w += hi.y;
}

// ---------------- mma helpers ----------------
__device__ __forceinline__ void ldm_x4(unsigned& a0, unsigned& a1, unsigned& a2, unsigned& a3, unsigned addr) {
    asm volatile("ldmatrix.sync.aligned.m8n8.x4.shared.b16 {%0,%1,%2,%3}, [%4];"
                 : "=r"(a0), "=r"(a1), "=r"(a2), "=r"(a3) : "r"(addr));
}
// B stored [n][k] row-major is already K-major ("col-major B") -> NON-trans ldmatrix
__device__ __forceinline__ void ldm_x2(unsigned& b0, unsigned& b1, unsigned addr) {
    asm volatile("ldmatrix.sync.aligned.m8n8.x2.shared.b16 {%0,%1}, [%2];"
                 : "=r"(b0), "=r"(b1) : "r"(addr));
}
__device__ __forceinline__ void mma16816(float* c, unsigned a0, unsigned a1, unsigned a2, unsigned a3,
                                         unsigned b0, unsigned b1) {
    asm volatile("mma.sync.aligned.m16n8k16.row.col.f32.f16.f16.f32 "
                 "{%0,%1,%2,%3}, {%4,%5,%6,%7}, {%8,%9}, {%0,%1,%2,%3};"
                 : "+f"(c[0]), "+f"(c[1]), "+f"(c[2]), "+f"(c[3])
                 : "r"(a0), "r"(a1), "r"(a2), "r"(a3), "r"(b0), "r"(b1));
}

// ---------------- CSR build ----------------
// g_cnt is zero before this kernel on every launch: statically zero-initialized, and
// fill_csr's reverse cursor returns it to zero at the end of every launch.
__global__ void count_edges(const int* __restrict__ ei, int E) {
    int e = blockIdx.x * blockDim.x + threadIdx.x;
    if (e == 0) g_tile = 0;                  // reset tile cursor for conv1gemm2
    if (e < E) atomicAdd(&g_cnt[ei[E + e]], 1);
}
__global__ void scan_partial(int N) {
    __shared__ int sh[SCAN_BS];
    int t = threadIdx.x;
    int i = blockIdx.x * SCAN_BS + t;
    sh[t] = (i < N) ? g_cnt[i] : 0;
    __syncthreads();
    for (int off = SCAN_BS / 2; off; off >>= 1) {
        if (t < off) sh[t] += sh[t + off];
        __syncthreads();
    }
    if (t == 0) g_bsum[blockIdx.x] = sh[0];
}
// scan_final also (redundantly per block) scans the block sums -> no scan_bsums kernel.
__global__ void scan_final(int N, int E, int NB) {
    __shared__ int sh[SCAN_BS];
    __shared__ int sbs[MAXNB];
    int t = threadIdx.x;
    if (t < MAXNB) sbs[t] = (t < NB) ? g_bsum[t] : 0;
    __syncthreads();
    for (int off = 1; off < MAXNB; off <<= 1) {
        int x = (t >= off && t < MAXNB) ? sbs[t - off] : 0;
        __syncthreads();
        if (t < MAXNB) sbs[t] += x;
        __syncthreads();
    }
    int boff = (blockIdx.x == 0) ? 0 : sbs[blockIdx.x - 1];

    int i = blockIdx.x * SCAN_BS + t;
    int v = (i < N) ? g_cnt[i] : 0;
    sh[t] = v;
    __syncthreads();
    for (int off = 1; off < SCAN_BS; off <<= 1) {
        int x = (t >= off) ? sh[t - off] : 0;
        __syncthreads();
        sh[t] += x;
        __syncthreads();
    }
    if (i < N) g_rowptr[i] = boff + sh[t] - v;   // exclusive scan; g_cnt stays = deg
    if (i == 0) g_rowptr[N] = E;
}
// Reverse-cursor fill: cnt goes deg -> 0, restoring the invariant for the next launch.
__global__ void fill_csr(const int* __restrict__ ei, int E) {
    int e = blockIdx.x * blockDim.x + threadIdx.x;
    if (e >= E) return;
    int s = ei[e], t = ei[E + e];
    int pos = atomicAdd(&g_cnt[t], -1);          // returns old count
    g_csr[g_rowptr[t] + pos - 1] = s;
}

// ---------------- conv0: gather@11 (half-warp per edge) + GEMM + LN + ReLU -> h0 (fp16) ----------------
__global__ void conv0_fused(const float* __restrict__ nf,
                            const float* __restrict__ W0, const float* __restrict__ b0,
                            const float* __restrict__ g0, const float* __restrict__ be0, int N) {
    __shared__ __align__(16) float sWt[FIN * HDIM];
    __shared__ __align__(16) float sb[HDIM], sg[HDIM], sbe[HDIM];
    for (int idx = threadIdx.x; idx < FIN * HDIM; idx += blockDim.x) {
        int i = idx >> 7, j = idx & 127;
        sWt[i * HDIM + j] = W0[j * FIN + i];
    }
    for (int i = threadIdx.x; i < HDIM; i += blockDim.x) { sb[i] = b0[i]; sg[i] = g0[i]; sbe[i] = be0[i]; }
    __syncthreads();
    int lane   = threadIdx.x & 31;
    int gwarp  = (blockIdx.x * blockDim.x + threadIdx.x) >> 5;
    int nwarps = (gridDim.x * blockDim.x) >> 5;
    int half = lane >> 4;      // 0: even CSR slots, 1: odd
    int f    = lane & 15;      // feature index
    bool lv  = f < FIN;
    for (int node = gwarp; node < N; node += nwarps) {
        int rp0 = g_rowptr[node], rp1 = g_rowptr[node + 1];
        int deg = rp1 - rp0;
        float a = 0.f;
        int j = rp0;
        for (; j + 7 < rp1; j += 8) {
            int s0 = g_csr[j + half],     s1 = g_csr[j + 2 + half];
            int s2 = g_csr[j + 4 + half], s3 = g_csr[j + 6 + half];
            float x0 = lv ? __ldg(nf + (long long)s0 * FIN + f) : 0.f;
            float x1 = lv ? __ldg(nf + (long long)s1 * FIN + f) : 0.f;
            float x2 = lv ? __ldg(nf + (long long)s2 * FIN + f) : 0.f;
            float x3 = lv ? __ldg(nf + (long long)s3 * FIN + f) : 0.f;
            a += (x0 + x1) + (x2 + x3);
        }
        for (; j + 1 < rp1; j += 2) {
            int s = g_csr[j + half];
            if (lv) a += __ldg(nf + (long long)s * FIN + f);
        }
        if (j < rp1 && half == 0) {
            int s = g_csr[j];
            if (lv) a += __ldg(nf + (long long)s * FIN + f);
        }
        float inv = deg > 0 ? 1.f / (float)deg : 0.f;
        float m[FIN];
#pragma unroll
        for (int i = 0; i < FIN; i++)
            m[i] = (__shfl_sync(0xffffffffu, a, i) + __shfl_sync(0xffffffffu, a, i + 16)) * inv;
        float mk = deg > 0 ? 1.f : 0.f;
        float4 vv = *(const float4*)&sb[lane * 4];
#pragma unroll
        for (int i = 0; i < FIN; i++) {
            float4 w = *(const float4*)&sWt[i * HDIM + lane * 4];
            vv.x = fmaf(m[i], w.x, vv.x); vv.y = fmaf(m[i], w.y, vv.y);
            vv.z = fmaf(m[i], w.z, vv.z); vv.w = fmaf(m[i], w.w, vv.w);
        }
        vv.x *= mk; vv.y *= mk; vv.z *= mk; vv.w *= mk;
        float s  = vv.x + vv.y + vv.z + vv.w;
        float s2 = vv.x * vv.x + vv.y * vv.y + vv.z * vv.z + vv.w * vv.w;
#pragma unroll
        for (int o = 16; o; o >>= 1) {
            s  += __shfl_xor_sync(0xffffffffu, s,  o);
            s2 += __shfl_xor_sync(0xffffffffu, s2, o);
        }
        float mu  = s * (1.f / HDIM);
        float var = s2 * (1.f / HDIM) - mu * mu;
        float rs  = rsqrtf(var + LNEPS);
        float4 g4  = *(const float4*)&sg[lane * 4];
        float4 be4 = *(const float4*)&sbe[lane * 4];
        float y0 = fmaxf((vv.x - mu) * rs * g4.x + be4.x, 0.f);
        float y1 = fmaxf((vv.y - mu) * rs * g4.y + be4.y, 0.f);
        float y2 = fmaxf((vv.z - mu) * rs * g4.z + be4.z, 0.f);
        float y3 = fmaxf((vv.w - mu) * rs * g4.w + be4.w, 0.f);
        __half2 hA = __float22half2_rn(make_float2(y0, y1));
        __half2 hB = __float22half2_rn(make_float2(y2, y3));
        uint2 u; u.x = *(unsigned*)&hA; u.y = *(unsigned*)&hB;
        g_h0h[(size_t)node * 32 + lane] = u;
    }
}

// ---------------- conv1+gemm2 tile kernel: dynamic tiles, gather(64) -> HMMA -> LN+ReLU -> HMMA ----------------
#define PITH 136
#define CG_SMEM 104448
#define CG_THREADS 512

__global__ void __launch_bounds__(CG_THREADS) conv1gemm2_mma(
    const float* __restrict__ W1, const float* __restrict__ b1,
    const float* __restrict__ g1, const float* __restrict__ be1,
    const float* __restrict__ W2, const float* __restrict__ b2, int N)
{
    extern __shared__ char smem[];
    __half* W1h = (__half*)(smem);
    __half* W2h = (__half*)(smem + 34816);
    __half* hA  = (__half*)(smem + 52224);
    float*  hC  = (float*)(smem + 69632);
    float*  sb1 = (float*)(smem + 102400);
    float*  sg1 = (float*)(smem + 102912);
    float*  sbe1= (float*)(smem + 103424);
    float*  sb2 = (float*)(smem + 103936);
    float*  smk = (float*)(smem + 104192);
    __shared__ int s_tile;
    unsigned sA_base  = (unsigned)__cvta_generic_to_shared(hA);
    unsigned sW1_base = (unsigned)__cvta_generic_to_shared(W1h);
    unsigned sW2_base = (unsigned)__cvta_generic_to_shared(W2h);

    int tid = threadIdx.x;
    for (int i = tid; i < HDIM * HDIM; i += CG_THREADS) {
        int j = i >> 7, k = i & 127;
        W1h[j * PITH + k] = __float2half(W1[i]);
    }
    for (int i = tid; i < DOUT * HDIM; i += CG_THREADS) {
        int j = i >> 7, k = i & 127;
        W2h[j * PITH + k] = __float2half(W2[i]);
    }
    for (int i = tid; i < HDIM; i += CG_THREADS) { sb1[i] = b1[i]; sg1[i] = g1[i]; sbe1[i] = be1[i]; }
    for (int i = tid; i < DOUT; i += CG_THREADS) sb2[i] = b2[i];
    if (tid == 0) s_tile = atomicAdd(&g_tile, 1);
    __syncthreads();

    int warp = tid >> 5, lane = tid & 31;
    int nTiles = (N + 63) >> 6;
    int tile = s_tile;
    while (tile < nTiles) {
        int tbase = tile << 6;

        // ---- Phase A: gather 4 nodes per warp into hA (fp16), MLP=8 ----
#pragma unroll
        for (int q = 0; q < 4; q++) {
            int nl = warp * 4 + q;
            int node = tbase + nl;
            float4 acc = make_float4(0.f, 0.f, 0.f, 0.f);
            float mk = 0.f;
            if (node < N) {
                int rp0 = g_rowptr[node], rp1 = g_rowptr[node + 1];
                int j = rp0;
                for (; j + 7 < rp1; j += 8) {
                    uint2 r0 = g_h0h[(size_t)g_csr[j]     * 32 + lane];
                    uint2 r1 = g_h0h[(size_t)g_csr[j + 1] * 32 + lane];
                    uint2 r2 = g_h0h[(size_t)g_csr[j + 2] * 32 + lane];
                    uint2 r3 = g_h0h[(size_t)g_csr[j + 3] * 32 + lane];
                    uint2 r4 = g_h0h[(size_t)g_csr[j + 4] * 32 + lane];
                    uint2 r5 = g_h0h[(size_t)g_csr[j + 5] * 32 + lane];
                    uint2 r6 = g_h0h[(size_t)g_csr[j + 6] * 32 + lane];
                    uint2 r7 = g_h0h[(size_t)g_csr[j + 7] * 32 + lane];
                    add_h4(acc, r0); add_h4(acc, r1); add_h4(acc, r2); add_h4(acc, r3);
                    add_h4(acc, r4); add_h4(acc, r5); add_h4(acc, r6); add_h4(acc, r7);
                }
                for (; j < rp1; j++) {
                    uint2 r = g_h0h[(size_t)g_csr[j] * 32 + lane];
                    add_h4(acc, r);
                }
                int deg = rp1 - rp0;
                float inv = deg > 0 ? 1.f / (float)deg : 0.f;
                mk = deg > 0 ? 1.f : 0.f;
                acc.x *= inv; acc.y *= inv; acc.z *= inv; acc.w *= inv;
            }
            __half2 hx = __float22half2_rn(make_float2(acc.x, acc.y));
            __half2 hy = __float22half2_rn(make_float2(acc.z, acc.w));
            uint2 u; u.x = *(unsigned*)&hx; u.y = *(unsigned*)&hy;
            *(uint2*)((char*)hA + nl * (PITH * 2) + lane * 8) = u;
            if (lane == 0) smk[nl] = mk;
        }
        __syncthreads();

        // ---- Phase B: GEMM1  hC[64][128] = hA[64][128] @ W1^T ----
        {
            int mt = warp & 3, nt = warp >> 2;
            int m0 = mt * 16, n0 = nt * 32;
            float C[4][4];
#pragma unroll
            for (int s = 0; s < 4; s++) { C[s][0] = C[s][1] = C[s][2] = C[s][3] = 0.f; }
            unsigned arow = (unsigned)(m0 + (lane & 15));
            unsigned akof = (unsigned)((lane >> 4) << 3);
#pragma unroll
            for (int k0 = 0; k0 < HDIM; k0 += 16) {
                unsigned a0, a1, a2, a3;
                ldm_x4(a0, a1, a2, a3, sA_base + (arow * PITH + k0 + akof) * 2);
#pragma unroll
                for (int s = 0; s < 4; s++) {
                    unsigned brow = (unsigned)(n0 + s * 8 + (lane & 7));
                    unsigned bkof = (unsigned)(k0 + ((lane >> 3) & 1) * 8);
                    unsigned b0, b1;
                    ldm_x2(b0, b1, sW1_base + (brow * PITH + bkof) * 2);
                    mma16816(C[s], a0, a1, a2, a3, b0, b1);
                }
            }
            int g = lane >> 2, cc = (lane & 3) * 2;
#pragma unroll
            for (int s = 0; s < 4; s++) {
                int col = n0 + s * 8 + cc;
                *(float2*)&hC[(m0 + g) * HDIM + col]     = make_float2(C[s][0], C[s][1]);
                *(float2*)&hC[(m0 + g + 8) * HDIM + col] = make_float2(C[s][2], C[s][3]);
            }
        }
        __syncthreads();

        // ---- Phase C: LN + ReLU per row, write fp16 back to hA ----
#pragma unroll
        for (int r = 0; r < 4; r++) {
            int row = warp * 4 + r;
            float4 v  = *(const float4*)&hC[row * HDIM + lane * 4];
            float4 b4 = *(const float4*)&sb1[lane * 4];
            float mk  = smk[row];
            float v0 = (v.x + b4.x) * mk, v1 = (v.y + b4.y) * mk;
            float v2 = (v.z + b4.z) * mk, v3 = (v.w + b4.w) * mk;
            float s  = v0 + v1 + v2 + v3;
            float s2 = v0 * v0 + v1 * v1 + v2 * v2 + v3 * v3;
#pragma unroll
            for (int o = 16; o; o >>= 1) {
                s  += __shfl_xor_sync(0xffffffffu, s,  o);
                s2 += __shfl_xor_sync(0xffffffffu, s2, o);
            }
            float mu  = s * (1.f / HDIM);
            float var = s2 * (1.f / HDIM) - mu * mu;
            float rs  = rsqrtf(var + LNEPS);
            float4 g4  = *(const float4*)&sg1[lane * 4];
            float4 be4 = *(const float4*)&sbe1[lane * 4];
            float y0 = fmaxf((v0 - mu) * rs * g4.x + be4.x, 0.f);
            float y1 = fmaxf((v1 - mu) * rs * g4.y + be4.y, 0.f);
            float y2 = fmaxf((v2 - mu) * rs * g4.z + be4.z, 0.f);
            float y3 = fmaxf((v3 - mu) * rs * g4.w + be4.w, 0.f);
            __half2 h01 = __float22half2_rn(make_float2(y0, y1));
            __half2 h23 = __float22half2_rn(make_float2(y2, y3));
            uint2 u; u.x = *(unsigned*)&h01; u.y = *(unsigned*)&h23;
            *(uint2*)((char*)hA + row * (PITH * 2) + lane * 8) = u;
        }
        __syncthreads();

        // ---- Phase D: GEMM2  xt2[64][64] = h1[64][128] @ W2^T + b2, store fp16 to global ----
        {
            int mt = warp & 3, nt = warp >> 2;
            int m0 = mt * 16, n0 = nt * 16;
            float C[2][4];
#pragma unroll
            for (int s = 0; s < 2; s++) { C[s][0] = C[s][1] = C[s][2] = C[s][3] = 0.f; }
            unsigned arow = (unsigned)(m0 + (lane & 15));
            unsigned akof = (unsigned)((lane >> 4) << 3);
#pragma unroll
            for (int k0 = 0; k0 < HDIM; k0 += 16) {
                unsigned a0, a1, a2, a3;
                ldm_x4(a0, a1, a2, a3, sA_base + (arow * PITH + k0 + akof) * 2);
#pragma unroll
                for (int s = 0; s < 2; s++) {
                    unsigned brow = (unsigned)(n0 + s * 8 + (lane & 7));
                    unsigned bkof = (unsigned)(k0 + ((lane >> 3) & 1) * 8);
                    unsigned b0, b1;
                    ldm_x2(b0, b1, sW2_base + (brow * PITH + bkof) * 2);
                    mma16816(C[s], a0, a1, a2, a3, b0, b1);
                }
            }
            int g = lane >> 2, cc = (lane & 3) * 2;
#pragma unroll
            for (int s = 0; s < 2; s++) {
                int col = n0 + s * 8 + cc;
                float bx = sb2[col], by = sb2[col + 1];
                int r0 = tbase + m0 + g, r1 = r0 + 8;
                if (r0 < N) {
                    __half2 h = __float22half2_rn(make_float2(C[s][0] + bx, C[s][1] + by));
                    g_xt2h[(size_t)r0 * 32 + (col >> 1)] = *(unsigned*)&h;
                }
                if (r1 < N) {
                    __half2 h = __float22half2_rn(make_float2(C[s][2] + bx, C[s][3] + by));
                    g_xt2h[(size_t)r1 * 32 + (col >> 1)] = *(unsigned*)&h;
                }
            }
        }
        if (tid == 0) s_tile = atomicAdd(&g_tile, 1);
        __syncthreads();   // hA reuse barrier + publishes s_tile
        tile = s_tile;
    }
}

// ---------------- final: gather xt2(fp16) -> LN -> out, warp per node, MLP=8 ----------------
__global__ void final_fused(const float* __restrict__ g2, const float* __restrict__ be2,
                            float* __restrict__ out, int N) {
    int lane   = threadIdx.x & 31;
    int gwarp  = (blockIdx.x * blockDim.x + threadIdx.x) >> 5;
    int nwarps = (gridDim.x * blockDim.x) >> 5;
    float gA = g2[lane * 2], gB = g2[lane * 2 + 1];
    float bA = be2[lane * 2], bB = be2[lane * 2 + 1];
    for (int node = gwarp; node < N; node += nwarps) {
        int rp0 = g_rowptr[node], rp1 = g_rowptr[node + 1];
        int deg = rp1 - rp0;
        float2 acc = make_float2(0.f, 0.f);
        int j = rp0;
        for (; j + 7 < rp1; j += 8) {
            unsigned r0 = g_xt2h[(size_t)g_csr[j]     * 32 + lane];
            unsigned r1 = g_xt2h[(size_t)g_csr[j + 1] * 32 + lane];
            unsigned r2 = g_xt2h[(size_t)g_csr[j + 2] * 32 + lane];
            unsigned r3 = g_xt2h[(size_t)g_csr[j + 3] * 32 + lane];
            unsigned r4 = g_xt2h[(size_t)g_csr[j + 4] * 32 + lane];
            unsigned r5 = g_xt2h[(size_t)g_csr[j + 5] * 32 + lane];
            unsigned r6 = g_xt2h[(size_t)g_csr[j + 6] * 32 + lane];
            unsigned r7 = g_xt2h[(size_t)g_csr[j + 7] * 32 + lane];
            float2 v0 = __half22float2(*(__half2*)&r0);
            float2 v1 = __half22float2(*(__half2*)&r1);
            float2 v2 = __half22float2(*(__half2*)&r2);
            float2 v3 = __half22float2(*(__half2*)&r3);
            float2 v4 = __half22float2(*(__half2*)&r4);
            float2 v5 = __half22float2(*(__half2*)&r5);
            float2 v6 = __half22float2(*(__half2*)&r6);
            float2 v7 = __half22float2(*(__half2*)&r7);
            acc.x += ((v0.x + v1.x) + (v2.x + v3.x)) + ((v4.x + v5.x) + (v6.x + v7.x));
            acc.y += ((v0.y + v1.y) + (v2.y + v3.y)) + ((v4.y + v5.y) + (v6.y + v7.y));
        }
        for (; j < rp1; j++) {
            unsigned r = g_xt2h[(size_t)g_csr[j] * 32 + lane];
            float2 v = __half22float2(*(__half2*)&r);
            acc.x += v.x; acc.y += v.y;
        }
        float inv = deg > 0 ? 1.f / (float)deg : 1.f;
        acc.x *= inv; acc.y *= inv;
        float s  = acc.x + acc.y;
        float s2 = acc.x * acc.x + acc.y * acc.y;
#pragma unroll
        for (int o = 16; o; o >>= 1) {
            s  += __shfl_xor_sync(0xffffffffu, s,  o);
            s2 += __shfl_xor_sync(0xffffffffu, s2, o);
        }
        float mu  = s * (1.f / DOUT);
        float var = s2 * (1.f / DOUT) - mu * mu;
        float rs  = rsqrtf(var + LNEPS);
        float2 o2;
        o2.x = (acc.x - mu) * rs * gA + bA;
        o2.y = (acc.y - mu) * rs * gB + bB;
        *(float2*)(out + (long long)node * DOUT + lane * 2) = o2;
    }
}

// ---------------- launch ----------------
extern "C" void kernel_launch(void* const* d_in, const int* in_sizes, int n_in,
                              void* d_out, int out_size) {
    const float* nf  = (const float*)d_in[0];
    const int*   ei  = (const int*)d_in[1];
    const float* W0  = (const float*)d_in[2];
    const float* b0  = (const float*)d_in[3];
    const float* W1  = (const float*)d_in[4];
    const float* b1  = (const float*)d_in[5];
    const float* W2  = (const float*)d_in[6];
    const float* b2  = (const float*)d_in[7];
    const float* g0  = (const float*)d_in[8];
    const float* be0 = (const float*)d_in[9];
    const float* g1  = (const float*)d_in[10];
    const float* be1 = (const float*)d_in[11];
    const float* g2  = (const float*)d_in[12];
    const float* be2 = (const float*)d_in[13];
    int N = in_sizes[0] / FIN;
    int E = in_sizes[1] / 2;
    int NB = (N + SCAN_BS - 1) / SCAN_BS;

    cudaFuncSetAttribute(conv1gemm2_mma, cudaFuncAttributeMaxDynamicSharedMemorySize, CG_SMEM);

    // CSR build (incoming edges grouped by target) — 4 launches
    count_edges<<<(E + 255) / 256, 256>>>(ei, E);
    scan_partial<<<NB, SCAN_BS>>>(N);
    scan_final<<<NB, SCAN_BS>>>(N, E, NB);
    fill_csr<<<(E + 255) / 256, 256>>>(ei, E);

    // layers
    conv0_fused<<<1480, 256>>>(nf, W0, b0, g0, be0, N);
    conv1gemm2_mma<<<304, CG_THREADS, CG_SMEM>>>(W1, b1, g1, be1, W2, b2, N);
    final_fused<<<1480, 256>>>(g2, be2, (float*)d_out, N);
}